// round 1
// baseline (speedup 1.0000x reference)
#include <cuda_runtime.h>
#include <cuda_bf16.h>
#include <cstddef>

// Problem constants
#define BB   2048
#define SS   100
#define FIN  158
#define DD   512
#define HH   8
#define HD   64
#define MM   (BB*SS)           // 204800 rows

// ---------------------------------------------------------------------------
// Scratch (device globals; no allocation allowed)
// ---------------------------------------------------------------------------
__device__ float g_X[(size_t)MM * DD];   // X / attn / y2
__device__ float g_Q[(size_t)MM * DD];   // Q / attn_out / H(temporal)
__device__ float g_K[(size_t)MM * DD];   // K / y1
__device__ float g_V[(size_t)MM * DD];   // V / ffn_out
__device__ float g_Hh[(size_t)MM * FIN]; // FFN hidden (relu)

// ---------------------------------------------------------------------------
// SGEMM: C[M,N] = A[M,K] @ W[N,K]^T (+ epilogue)
// BM=BN=128, BK=8, 256 threads, 8x8 per thread.
// EPI: 0=bias, 1=bias+PE, 2=bias+relu, 3=none
// ---------------------------------------------------------------------------
template <int EPI>
__global__ __launch_bounds__(256)
void sgemm_kernel(const float* __restrict__ A, const float* __restrict__ W,
                  const float* __restrict__ bias, const float* __restrict__ pe,
                  float* __restrict__ C, int M, int N, int K)
{
    __shared__ float As[8][128];
    __shared__ float Bs[8][128];

    const int t  = threadIdx.x;
    const int bm = blockIdx.y * 128;
    const int bn = blockIdx.x * 128;
    const int tx = t & 15;        // 0..15 -> 8 cols each
    const int ty = t >> 4;        // 0..15 -> 8 rows each

    float acc[8][8];
#pragma unroll
    for (int i = 0; i < 8; i++)
#pragma unroll
        for (int j = 0; j < 8; j++) acc[i][j] = 0.f;

    for (int k0 = 0; k0 < K; k0 += 8) {
        // Load A tile (1024 elems / 256 thr = 4 each), store transposed
#pragma unroll
        for (int i = 0; i < 4; i++) {
            int e = t + i * 256;
            int m = e >> 3, k = e & 7;
            int gk = k0 + k;
            float v = 0.f;
            if (gk < K) v = A[(size_t)(bm + m) * K + gk];
            As[k][m] = v;
        }
        // Load W tile (as B^T)
#pragma unroll
        for (int i = 0; i < 4; i++) {
            int e = t + i * 256;
            int n = e >> 3, k = e & 7;
            int gn = bn + n, gk = k0 + k;
            float v = 0.f;
            if (gn < N && gk < K) v = W[(size_t)gn * K + gk];
            Bs[k][n] = v;
        }
        __syncthreads();

#pragma unroll
        for (int kk = 0; kk < 8; kk++) {
            float a[8], b[8];
#pragma unroll
            for (int i = 0; i < 8; i++) a[i] = As[kk][ty * 8 + i];
#pragma unroll
            for (int j = 0; j < 8; j++) b[j] = Bs[kk][tx * 8 + j];
#pragma unroll
            for (int i = 0; i < 8; i++)
#pragma unroll
                for (int j = 0; j < 8; j++) acc[i][j] += a[i] * b[j];
        }
        __syncthreads();
    }

#pragma unroll
    for (int i = 0; i < 8; i++) {
        int gm = bm + ty * 8 + i;
        int smod = gm % SS;  // row's time index (for PE)
#pragma unroll
        for (int j = 0; j < 8; j++) {
            int gn = bn + tx * 8 + j;
            if (gn < N) {
                float v = acc[i][j];
                if (EPI != 3) v += bias[gn];
                if (EPI == 1) v += pe[(size_t)smod * DD + gn];
                if (EPI == 2) v = fmaxf(v, 0.f);
                C[(size_t)gm * N + gn] = v;
            }
        }
    }
}

// ---------------------------------------------------------------------------
// Attention: one block per (b, h). 128 threads; threads 0..99 own q rows.
// SMEM: K tile (100x64), V tile (100x64), scores (100x101 padded).
// ---------------------------------------------------------------------------
#define ATT_SMEM ((6400 + 6400 + 100 * 101) * 4)

__global__ __launch_bounds__(128)
void attn_kernel(const float* __restrict__ Q, const float* __restrict__ K,
                 const float* __restrict__ V, float* __restrict__ O)
{
    extern __shared__ float sm[];
    float* Ks = sm;
    float* Vs = sm + 6400;
    float* Sc = sm + 12800;      // stride 101

    const int bh = blockIdx.x;
    const int b  = bh >> 3;
    const int h  = bh & 7;
    const size_t base = ((size_t)b * SS) * DD + (size_t)h * HD;
    const int t = threadIdx.x;

    // cooperative K/V tile load (float4)
    for (int i = t; i < SS * (HD / 4); i += 128) {
        int s = i >> 4, d4 = i & 15;
        const size_t g = base + (size_t)s * DD + d4 * 4;
        ((float4*)Ks)[i] = *(const float4*)&K[g];
        ((float4*)Vs)[i] = *(const float4*)&V[g];
    }
    __syncthreads();

    if (t < SS) {
        float q[HD];
        const float* qp = &Q[base + (size_t)t * DD];
#pragma unroll
        for (int d = 0; d < HD; d++) q[d] = qp[d];

        float mx = -1e30f;
        for (int j = 0; j < SS; j++) {
            const float* kp = &Ks[j * HD];
            float s_ = 0.f;
#pragma unroll
            for (int d = 0; d < HD; d++) s_ += q[d] * kp[d];
            s_ *= 0.125f;                 // 1/sqrt(64)
            Sc[t * 101 + j] = s_;
            mx = fmaxf(mx, s_);
        }
        float sum = 0.f;
        for (int j = 0; j < SS; j++) {
            float e = __expf(Sc[t * 101 + j] - mx);
            Sc[t * 101 + j] = e;
            sum += e;
        }
        const float inv = 1.f / sum;

        float out[HD];
#pragma unroll
        for (int d = 0; d < HD; d++) out[d] = 0.f;
        for (int j = 0; j < SS; j++) {
            float p = Sc[t * 101 + j] * inv;
            const float* vp = &Vs[j * HD];
#pragma unroll
            for (int d = 0; d < HD; d++) out[d] += p * vp[d];
        }
        float* op = &O[base + (size_t)t * DD];
#pragma unroll
        for (int d = 0; d < HD; d++) op[d] = out[d];
    }
}

// ---------------------------------------------------------------------------
// AddNorm: Y = X + LayerNorm(X)*w + b   (one block per row of 512)
// ---------------------------------------------------------------------------
__global__ __launch_bounds__(128)
void addnorm_kernel(const float* __restrict__ X, const float* __restrict__ w,
                    const float* __restrict__ bn, float* __restrict__ Y)
{
    const int row = blockIdx.x;
    const float* x = X + (size_t)row * DD;
    const int t = threadIdx.x;

    float v[4];
    float s = 0.f, s2 = 0.f;
#pragma unroll
    for (int i = 0; i < 4; i++) {
        v[i] = x[t + 128 * i];
        s  += v[i];
        s2 += v[i] * v[i];
    }
#pragma unroll
    for (int o = 16; o > 0; o >>= 1) {
        s  += __shfl_down_sync(0xffffffffu, s,  o);
        s2 += __shfl_down_sync(0xffffffffu, s2, o);
    }
    __shared__ float red[66];
    const int wid = t >> 5, lid = t & 31;
    if (lid == 0) { red[wid] = s; red[32 + wid] = s2; }
    __syncthreads();
    if (t == 0) {
        float a = 0.f, c = 0.f;
        for (int i = 0; i < 4; i++) { a += red[i]; c += red[32 + i]; }
        red[64] = a; red[65] = c;
    }
    __syncthreads();
    const float mu  = red[64] * (1.f / DD);
    const float var = red[65] * (1.f / DD) - mu * mu;
    const float rs  = rsqrtf(var + 1e-5f);

    float* y = Y + (size_t)row * DD;
#pragma unroll
    for (int i = 0; i < 4; i++) {
        int c = t + 128 * i;
        y[c] = v[i] + (v[i] - mu) * rs * w[c] + bn[c];
    }
}

// ---------------------------------------------------------------------------
// Pooling: per batch b.
//   lam_s = <H[b,s], H[b,S-1]>;  p = softmax(lam)
//   out[b] = sum_s p_s * <Y2[b,s], Wout>  + bout      (pooled never formed)
// ---------------------------------------------------------------------------
__global__ __launch_bounds__(256)
void pool_kernel(const float* __restrict__ Y2, const float* __restrict__ Hm,
                 const float* __restrict__ Wout, const float* __restrict__ bout,
                 float* __restrict__ out)
{
    const int b = blockIdx.x;
    const int t = threadIdx.x;   // 256 = 8 warps
    __shared__ float hl[DD];
    __shared__ float lam[SS];
    __shared__ float g[SS];

    const float* Hb = Hm + (size_t)b * SS * DD;
    const float* Yb = Y2 + (size_t)b * SS * DD;

    for (int i = t; i < DD; i += 256) hl[i] = Hb[(size_t)(SS - 1) * DD + i];
    __syncthreads();

    const int wid = t >> 5, lid = t & 31;
    for (int s = wid; s < SS; s += 8) {
        const float* hr = Hb + (size_t)s * DD;
        const float* yr = Yb + (size_t)s * DD;
        float a = 0.f, c = 0.f;
        for (int d = lid; d < DD; d += 32) {
            a += hr[d] * hl[d];
            c += yr[d] * Wout[d];
        }
#pragma unroll
        for (int o = 16; o > 0; o >>= 1) {
            a += __shfl_down_sync(0xffffffffu, a, o);
            c += __shfl_down_sync(0xffffffffu, c, o);
        }
        if (lid == 0) { lam[s] = a; g[s] = c; }
    }
    __syncthreads();

    if (t < 32) {
        float mx = -1e30f;
        for (int s = t; s < SS; s += 32) mx = fmaxf(mx, lam[s]);
#pragma unroll
        for (int o = 16; o > 0; o >>= 1) mx = fmaxf(mx, __shfl_xor_sync(0xffffffffu, mx, o));
        float se = 0.f, sg = 0.f;
        for (int s = t; s < SS; s += 32) {
            float e = __expf(lam[s] - mx);
            se += e;
            sg += e * g[s];
        }
#pragma unroll
        for (int o = 16; o > 0; o >>= 1) {
            se += __shfl_xor_sync(0xffffffffu, se, o);
            sg += __shfl_xor_sync(0xffffffffu, sg, o);
        }
        if (t == 0) out[b] = sg / se + bout[0];
    }
}

// ---------------------------------------------------------------------------
// Launch
// ---------------------------------------------------------------------------
extern "C" void kernel_launch(void* const* d_in, const int* in_sizes, int n_in,
                              void* d_out, int out_size)
{
    const float* src  = (const float*)d_in[0];
    const float* Wf   = (const float*)d_in[1];
    const float* bf   = (const float*)d_in[2];
    const float* pe   = (const float*)d_in[3];
    const float* Wq   = (const float*)d_in[4];
    const float* bq   = (const float*)d_in[5];
    const float* Wk   = (const float*)d_in[6];
    const float* bk   = (const float*)d_in[7];
    const float* Wv   = (const float*)d_in[8];
    const float* bv   = (const float*)d_in[9];
    const float* Wo   = (const float*)d_in[10];
    const float* bo   = (const float*)d_in[11];
    const float* lnw  = (const float*)d_in[12];
    const float* lnb  = (const float*)d_in[13];
    const float* W1   = (const float*)d_in[14];
    const float* b1   = (const float*)d_in[15];
    const float* W2   = (const float*)d_in[16];
    const float* b2   = (const float*)d_in[17];
    const float* Wt   = (const float*)d_in[18];
    const float* Wout = (const float*)d_in[19];
    const float* bout = (const float*)d_in[20];
    float* out = (float*)d_out;

    float *X, *Q, *Kb, *V, *Hh;
    cudaGetSymbolAddress((void**)&X,  g_X);
    cudaGetSymbolAddress((void**)&Q,  g_Q);
    cudaGetSymbolAddress((void**)&Kb, g_K);
    cudaGetSymbolAddress((void**)&V,  g_V);
    cudaGetSymbolAddress((void**)&Hh, g_Hh);

    cudaFuncSetAttribute(attn_kernel, cudaFuncAttributeMaxDynamicSharedMemorySize, ATT_SMEM);

    const dim3 g512((DD + 127) / 128, MM / 128);   // N=512 GEMMs
    const dim3 g158((FIN + 127) / 128, MM / 128);  // N=158 GEMM
    const dim3 b256(256);

    // 1) X = src @ Wf^T + bf + PE
    sgemm_kernel<1><<<g512, b256>>>(src, Wf, bf, pe, X, MM, DD, FIN);
    // 2) Q,K,V
    sgemm_kernel<0><<<g512, b256>>>(X, Wq, bq, nullptr, Q,  MM, DD, DD);
    sgemm_kernel<0><<<g512, b256>>>(X, Wk, bk, nullptr, Kb, MM, DD, DD);
    sgemm_kernel<0><<<g512, b256>>>(X, Wv, bv, nullptr, V,  MM, DD, DD);
    // 3) attention -> X (X is dead now)
    attn_kernel<<<BB * HH, 128, ATT_SMEM>>>(Q, Kb, V, X);
    // 4) attn_out = attn @ Wo^T + bo -> Q
    sgemm_kernel<0><<<g512, b256>>>(X, Wo, bo, nullptr, Q, MM, DD, DD);
    // 5) y1 = attn_out + LN(attn_out) -> K buffer
    addnorm_kernel<<<MM, 128>>>(Q, lnw, lnb, Kb);
    // 6) hidden = relu(y1 @ W1^T + b1) -> Hh
    sgemm_kernel<2><<<g158, b256>>>(Kb, W1, b1, nullptr, Hh, MM, FIN, DD);
    // 7) ffn = hidden @ W2^T + b2 -> V
    sgemm_kernel<0><<<g512, b256>>>(Hh, W2, b2, nullptr, V, MM, DD, FIN);
    // 8) y2 = ffn + LN(ffn) -> X
    addnorm_kernel<<<MM, 128>>>(V, lnw, lnb, X);
    // 9) H = y2 @ Wt^T (no bias) -> Q
    sgemm_kernel<3><<<g512, b256>>>(X, Wt, nullptr, nullptr, Q, MM, DD, DD);
    // 10) temporal pooling + final projection -> out [B,1]
    pool_kernel<<<BB, 256>>>(X, Q, Wout, bout, out);
}

// round 6
// speedup vs baseline: 1.7011x; 1.7011x over previous
#include <cuda_runtime.h>
#include <cuda_bf16.h>
#include <cstdint>
#include <cstddef>

// Problem constants
#define BB   2048
#define SS   100
#define FIN  158
#define DD   512
#define HH   8
#define HD   64
#define MM   (BB*SS)           // 204800 rows

// ---------------------------------------------------------------------------
// Scratch (device globals; no allocation allowed)
// ---------------------------------------------------------------------------
__device__ float g_X[(size_t)MM * DD];   // X / attn / y2
__device__ float g_Q[(size_t)MM * DD];   // Q / attn_out / H(temporal)
__device__ float g_K[(size_t)MM * DD];   // K / y1
__device__ float g_V[(size_t)MM * DD];   // V / ffn_out
__device__ float g_Hh[(size_t)MM * FIN]; // FFN hidden (relu)

// ---------------------------------------------------------------------------
// TF32 tensor-core GEMM: C[M,N] = A[M,K] @ W[N,K]^T (+ epilogue)
// BM=BN=128, BK=16, 256 threads (8 warps: 2x4), warp tile 64x32,
// mma.sync.m16n8k8.tf32, fp32 accumulate. 2-stage smem double buffer.
// EPI: 0=bias, 1=bias+PE, 2=bias+relu, 3=none
// ---------------------------------------------------------------------------
template <int EPI>
__global__ __launch_bounds__(256)
void tgemm_kernel(const float* __restrict__ A, const float* __restrict__ W,
                  const float* __restrict__ bias, const float* __restrict__ pe,
                  float* __restrict__ C, int M, int N, int K)
{
    // [stage][row][k] with +4 padding -> conflict-free fragment loads
    __shared__ uint32_t As[2][128][20];
    __shared__ uint32_t Bs[2][128][20];

    const int t    = threadIdx.x;
    const int bm   = blockIdx.y * 128;
    const int bn   = blockIdx.x * 128;
    const int wid  = t >> 5;
    const int lane = t & 31;
    const int wm   = (wid >> 2) * 64;   // warp row base (0 or 64)
    const int wn   = (wid & 3) * 32;    // warp col base (0,32,64,96)
    const int lr   = lane >> 2;         // 0..7
    const int lc   = lane & 3;          // 0..3

    float acc[4][4][4];
#pragma unroll
    for (int i = 0; i < 4; i++)
#pragma unroll
        for (int j = 0; j < 4; j++)
#pragma unroll
            for (int r = 0; r < 4; r++) acc[i][j][r] = 0.f;

    const int nt = (K + 15) / 16;

    uint32_t ar[8], br[8];

    // stage elements: e = t + i*256 ; m = e>>4 (row 0..127), k = e&15
    auto gload = [&](int k0) {
#pragma unroll
        for (int i = 0; i < 8; i++) {
            int e = t + i * 256;
            int m = e >> 4, k = e & 15;
            int gk = k0 + k;
            float va = 0.f, vb = 0.f;
            if (gk < K) {
                va = A[(size_t)(bm + m) * K + gk];
                int gn = bn + m;
                if (gn < N) vb = W[(size_t)gn * K + gk];
            }
            asm("cvt.rna.tf32.f32 %0, %1;" : "=r"(ar[i]) : "f"(va));
            asm("cvt.rna.tf32.f32 %0, %1;" : "=r"(br[i]) : "f"(vb));
        }
    };
    auto sstore = [&](int s) {
#pragma unroll
        for (int i = 0; i < 8; i++) {
            int e = t + i * 256;
            int m = e >> 4, k = e & 15;
            As[s][m][k] = ar[i];
            Bs[s][m][k] = br[i];
        }
    };

    gload(0);
    sstore(0);
    __syncthreads();

    for (int kt = 0; kt < nt; kt++) {
        const int s = kt & 1;
        if (kt + 1 < nt) gload((kt + 1) * 16);

#pragma unroll
        for (int ks = 0; ks < 2; ks++) {
            const int kb = ks * 8;
            uint32_t af[4][4];
#pragma unroll
            for (int i = 0; i < 4; i++) {
                int r = wm + i * 16 + lr;
                af[i][0] = As[s][r][kb + lc];
                af[i][1] = As[s][r + 8][kb + lc];
                af[i][2] = As[s][r][kb + lc + 4];
                af[i][3] = As[s][r + 8][kb + lc + 4];
            }
            uint32_t bf[4][2];
#pragma unroll
            for (int j = 0; j < 4; j++) {
                int c = wn + j * 8 + lr;
                bf[j][0] = Bs[s][c][kb + lc];
                bf[j][1] = Bs[s][c][kb + lc + 4];
            }
#pragma unroll
            for (int i = 0; i < 4; i++)
#pragma unroll
                for (int j = 0; j < 4; j++) {
                    asm volatile(
                        "mma.sync.aligned.m16n8k8.row.col.f32.tf32.tf32.f32 "
                        "{%0,%1,%2,%3}, {%4,%5,%6,%7}, {%8,%9}, {%0,%1,%2,%3};\n"
                        : "+f"(acc[i][j][0]), "+f"(acc[i][j][1]),
                          "+f"(acc[i][j][2]), "+f"(acc[i][j][3])
                        : "r"(af[i][0]), "r"(af[i][1]), "r"(af[i][2]), "r"(af[i][3]),
                          "r"(bf[j][0]), "r"(bf[j][1]));
                }
        }

        if (kt + 1 < nt) sstore((kt + 1) & 1);
        __syncthreads();
    }

    // Epilogue. mma C layout: c0,c1 -> row lr, cols 2*lc, 2*lc+1 ; c2,c3 -> row lr+8
#pragma unroll
    for (int i = 0; i < 4; i++) {
        int r0 = bm + wm + i * 16 + lr;
#pragma unroll
        for (int j = 0; j < 4; j++) {
            int c = bn + wn + j * 8 + lc * 2;
            if (c < N) {
                float v00 = acc[i][j][0], v01 = acc[i][j][1];
                float v10 = acc[i][j][2], v11 = acc[i][j][3];
                if (EPI != 3) {
                    float b0 = bias[c], b1 = bias[c + 1];
                    v00 += b0; v01 += b1; v10 += b0; v11 += b1;
                }
                if (EPI == 1) {
                    int s0 = r0 % SS, s1 = (r0 + 8) % SS;
                    v00 += pe[(size_t)s0 * DD + c];
                    v01 += pe[(size_t)s0 * DD + c + 1];
                    v10 += pe[(size_t)s1 * DD + c];
                    v11 += pe[(size_t)s1 * DD + c + 1];
                }
                if (EPI == 2) {
                    v00 = fmaxf(v00, 0.f); v01 = fmaxf(v01, 0.f);
                    v10 = fmaxf(v10, 0.f); v11 = fmaxf(v11, 0.f);
                }
                *(float2*)&C[(size_t)r0 * N + c] = make_float2(v00, v01);
                *(float2*)&C[(size_t)(r0 + 8) * N + c] = make_float2(v10, v11);
            }
        }
    }
}

// ---------------------------------------------------------------------------
// Attention: one block per (b, h). 128 threads; threads 0..99 own q rows.
// ---------------------------------------------------------------------------
#define ATT_SMEM ((6400 + 6400 + 100 * 101) * 4)

__global__ __launch_bounds__(128)
void attn_kernel(const float* __restrict__ Q, const float* __restrict__ K,
                 const float* __restrict__ V, float* __restrict__ O)
{
    extern __shared__ float sm[];
    float* Ks = sm;
    float* Vs = sm + 6400;
    float* Sc = sm + 12800;      // stride 101

    const int bh = blockIdx.x;
    const int b  = bh >> 3;
    const int h  = bh & 7;
    const size_t base = ((size_t)b * SS) * DD + (size_t)h * HD;
    const int t = threadIdx.x;

    for (int i = t; i < SS * (HD / 4); i += 128) {
        int s = i >> 4, d4 = i & 15;
        const size_t g = base + (size_t)s * DD + d4 * 4;
        ((float4*)Ks)[i] = *(const float4*)&K[g];
        ((float4*)Vs)[i] = *(const float4*)&V[g];
    }
    __syncthreads();

    if (t < SS) {
        float q[HD];
        const float* qp = &Q[base + (size_t)t * DD];
#pragma unroll
        for (int d = 0; d < HD; d++) q[d] = qp[d];

        float mx = -1e30f;
        for (int j = 0; j < SS; j++) {
            const float* kp = &Ks[j * HD];
            float s_ = 0.f;
#pragma unroll
            for (int d = 0; d < HD; d++) s_ += q[d] * kp[d];
            s_ *= 0.125f;
            Sc[t * 101 + j] = s_;
            mx = fmaxf(mx, s_);
        }
        float sum = 0.f;
        for (int j = 0; j < SS; j++) {
            float e = __expf(Sc[t * 101 + j] - mx);
            Sc[t * 101 + j] = e;
            sum += e;
        }
        const float inv = 1.f / sum;

        float out[HD];
#pragma unroll
        for (int d = 0; d < HD; d++) out[d] = 0.f;
        for (int j = 0; j < SS; j++) {
            float p = Sc[t * 101 + j] * inv;
            const float* vp = &Vs[j * HD];
#pragma unroll
            for (int d = 0; d < HD; d++) out[d] += p * vp[d];
        }
        float* op = &O[base + (size_t)t * DD];
#pragma unroll
        for (int d = 0; d < HD; d++) op[d] = out[d];
    }
}

// ---------------------------------------------------------------------------
// AddNorm: Y = X + LayerNorm(X)*w + b   (one block per row of 512)
// ---------------------------------------------------------------------------
__global__ __launch_bounds__(128)
void addnorm_kernel(const float* __restrict__ X, const float* __restrict__ w,
                    const float* __restrict__ bn, float* __restrict__ Y)
{
    const int row = blockIdx.x;
    const float* x = X + (size_t)row * DD;
    const int t = threadIdx.x;

    float v[4];
    float s = 0.f, s2 = 0.f;
#pragma unroll
    for (int i = 0; i < 4; i++) {
        v[i] = x[t + 128 * i];
        s  += v[i];
        s2 += v[i] * v[i];
    }
#pragma unroll
    for (int o = 16; o > 0; o >>= 1) {
        s  += __shfl_down_sync(0xffffffffu, s,  o);
        s2 += __shfl_down_sync(0xffffffffu, s2, o);
    }
    __shared__ float red[66];
    const int wid = t >> 5, lid = t & 31;
    if (lid == 0) { red[wid] = s; red[32 + wid] = s2; }
    __syncthreads();
    if (t == 0) {
        float a = 0.f, c = 0.f;
        for (int i = 0; i < 4; i++) { a += red[i]; c += red[32 + i]; }
        red[64] = a; red[65] = c;
    }
    __syncthreads();
    const float mu  = red[64] * (1.f / DD);
    const float var = red[65] * (1.f / DD) - mu * mu;
    const float rs  = rsqrtf(var + 1e-5f);

    float* y = Y + (size_t)row * DD;
#pragma unroll
    for (int i = 0; i < 4; i++) {
        int c = t + 128 * i;
        y[c] = v[i] + (v[i] - mu) * rs * w[c] + bn[c];
    }
}

// ---------------------------------------------------------------------------
// Pooling: per batch b.
// ---------------------------------------------------------------------------
__global__ __launch_bounds__(256)
void pool_kernel(const float* __restrict__ Y2, const float* __restrict__ Hm,
                 const float* __restrict__ Wout, const float* __restrict__ bout,
                 float* __restrict__ out)
{
    const int b = blockIdx.x;
    const int t = threadIdx.x;
    __shared__ float hl[DD];
    __shared__ float lam[SS];
    __shared__ float g[SS];

    const float* Hb = Hm + (size_t)b * SS * DD;
    const float* Yb = Y2 + (size_t)b * SS * DD;

    for (int i = t; i < DD; i += 256) hl[i] = Hb[(size_t)(SS - 1) * DD + i];
    __syncthreads();

    const int wid = t >> 5, lid = t & 31;
    for (int s = wid; s < SS; s += 8) {
        const float* hr = Hb + (size_t)s * DD;
        const float* yr = Yb + (size_t)s * DD;
        float a = 0.f, c = 0.f;
        for (int d = lid; d < DD; d += 32) {
            a += hr[d] * hl[d];
            c += yr[d] * Wout[d];
        }
#pragma unroll
        for (int o = 16; o > 0; o >>= 1) {
            a += __shfl_down_sync(0xffffffffu, a, o);
            c += __shfl_down_sync(0xffffffffu, c, o);
        }
        if (lid == 0) { lam[s] = a; g[s] = c; }
    }
    __syncthreads();

    if (t < 32) {
        float mx = -1e30f;
        for (int s = t; s < SS; s += 32) mx = fmaxf(mx, lam[s]);
#pragma unroll
        for (int o = 16; o > 0; o >>= 1) mx = fmaxf(mx, __shfl_xor_sync(0xffffffffu, mx, o));
        float se = 0.f, sg = 0.f;
        for (int s = t; s < SS; s += 32) {
            float e = __expf(lam[s] - mx);
            se += e;
            sg += e * g[s];
        }
#pragma unroll
        for (int o = 16; o > 0; o >>= 1) {
            se += __shfl_xor_sync(0xffffffffu, se, o);
            sg += __shfl_xor_sync(0xffffffffu, sg, o);
        }
        if (t == 0) out[b] = sg / se + bout[0];
    }
}

// ---------------------------------------------------------------------------
// Launch
// ---------------------------------------------------------------------------
extern "C" void kernel_launch(void* const* d_in, const int* in_sizes, int n_in,
                              void* d_out, int out_size)
{
    const float* src  = (const float*)d_in[0];
    const float* Wf   = (const float*)d_in[1];
    const float* bf   = (const float*)d_in[2];
    const float* pe   = (const float*)d_in[3];
    const float* Wq   = (const float*)d_in[4];
    const float* bq   = (const float*)d_in[5];
    const float* Wk   = (const float*)d_in[6];
    const float* bk   = (const float*)d_in[7];
    const float* Wv   = (const float*)d_in[8];
    const float* bv   = (const float*)d_in[9];
    const float* Wo   = (const float*)d_in[10];
    const float* bo   = (const float*)d_in[11];
    const float* lnw  = (const float*)d_in[12];
    const float* lnb  = (const float*)d_in[13];
    const float* W1   = (const float*)d_in[14];
    const float* b1   = (const float*)d_in[15];
    const float* W2   = (const float*)d_in[16];
    const float* b2   = (const float*)d_in[17];
    const float* Wt   = (const float*)d_in[18];
    const float* Wout = (const float*)d_in[19];
    const float* bout = (const float*)d_in[20];
    float* out = (float*)d_out;

    float *X, *Q, *Kb, *V, *Hh;
    cudaGetSymbolAddress((void**)&X,  g_X);
    cudaGetSymbolAddress((void**)&Q,  g_Q);
    cudaGetSymbolAddress((void**)&Kb, g_K);
    cudaGetSymbolAddress((void**)&V,  g_V);
    cudaGetSymbolAddress((void**)&Hh, g_Hh);

    cudaFuncSetAttribute(attn_kernel, cudaFuncAttributeMaxDynamicSharedMemorySize, ATT_SMEM);

    const dim3 g512((DD + 127) / 128, MM / 128);   // N=512 GEMMs
    const dim3 g158((FIN + 127) / 128, MM / 128);  // N=158 GEMM
    const dim3 b256(256);

    // 1) X = src @ Wf^T + bf + PE
    tgemm_kernel<1><<<g512, b256>>>(src, Wf, bf, pe, X, MM, DD, FIN);
    // 2) Q,K,V
    tgemm_kernel<0><<<g512, b256>>>(X, Wq, bq, nullptr, Q,  MM, DD, DD);
    tgemm_kernel<0><<<g512, b256>>>(X, Wk, bk, nullptr, Kb, MM, DD, DD);
    tgemm_kernel<0><<<g512, b256>>>(X, Wv, bv, nullptr, V,  MM, DD, DD);
    // 3) attention -> X (X dead)
    attn_kernel<<<BB * HH, 128, ATT_SMEM>>>(Q, Kb, V, X);
    // 4) attn_out = attn @ Wo^T + bo -> Q
    tgemm_kernel<0><<<g512, b256>>>(X, Wo, bo, nullptr, Q, MM, DD, DD);
    // 5) y1 = attn_out + LN(attn_out) -> Kb
    addnorm_kernel<<<MM, 128>>>(Q, lnw, lnb, Kb);
    // 6) hidden = relu(y1 @ W1^T + b1) -> Hh
    tgemm_kernel<2><<<g158, b256>>>(Kb, W1, b1, nullptr, Hh, MM, FIN, DD);
    // 7) ffn = hidden @ W2^T + b2 -> V
    tgemm_kernel<0><<<g512, b256>>>(Hh, W2, b2, nullptr, V, MM, DD, FIN);
    // 8) y2 = ffn + LN(ffn) -> X
    addnorm_kernel<<<MM, 128>>>(V, lnw, lnb, X);
    // 9) H = y2 @ Wt^T -> Q
    tgemm_kernel<3><<<g512, b256>>>(X, Wt, nullptr, nullptr, Q, MM, DD, DD);
    // 10) pooling + final projection
    pool_kernel<<<BB, 256>>>(X, Q, Wout, bout, out);
}

// round 9
// speedup vs baseline: 3.5559x; 2.0904x over previous
#include <cuda_runtime.h>
#include <cuda_bf16.h>
#include <cstdint>
#include <cstddef>

// Problem constants
#define BB   2048
#define SS   100
#define FIN  158
#define DD   512
#define HH   8
#define HD   64
#define MM   (BB*SS)           // 204800 rows

// ---------------------------------------------------------------------------
// Scratch (device globals; no allocation allowed)
// ---------------------------------------------------------------------------
__device__ float g_X[(size_t)MM * DD];   // X / attn / y2
__device__ float g_Q[(size_t)MM * DD];   // Q / attn_out / H(temporal)
__device__ float g_K[(size_t)MM * DD];   // K / y1
__device__ float g_V[(size_t)MM * DD];   // V / ffn_out
__device__ float g_Hh[(size_t)MM * FIN]; // FFN hidden (relu)

// ---------------------------------------------------------------------------
// Helpers
// ---------------------------------------------------------------------------
__device__ __forceinline__ uint32_t smem_u32(const void* p) {
    uint32_t a;
    asm("{ .reg .u64 t; cvta.to.shared.u64 t, %1; cvt.u32.u64 %0, t; }" : "=r"(a) : "l"(p));
    return a;
}
__device__ __forceinline__ void cp16(uint32_t dst, const void* src, int sz) {
    asm volatile("cp.async.cg.shared.global [%0], [%1], 16, %2;"
                 :: "r"(dst), "l"(src), "r"(sz));
}
__device__ __forceinline__ void cp8(uint32_t dst, const void* src, int sz) {
    asm volatile("cp.async.ca.shared.global [%0], [%1], 8, %2;"
                 :: "r"(dst), "l"(src), "r"(sz));
}
#define CP_COMMIT() asm volatile("cp.async.commit_group;" ::: "memory")
#define CP_WAIT1()  asm volatile("cp.async.wait_group 1;" ::: "memory")

// ---------------------------------------------------------------------------
// TF32 mma.sync GEMM with cp.async pipeline.
// C[M,N] = A[M,K] @ W[N,K]^T (+ epilogue)
// BM=BN=128, BK=16, 256 threads (8 warps: 2x4), warp tile 64x32.
// 4 smem slots, issue distance 2, one __syncthreads per tile.
// Chunk accounting: tile = 128 rows x 16 floats per matrix.
//   16B path: 4 chunks/row -> 512 chunks -> 2 per thread per matrix.
//   8B  path: 8 chunks/row -> 1024 chunks -> 4 per thread per matrix.
// smem slot: A[128][20] floats then B[128][20] floats -> 20480 B/slot, 80KB total.
// EPI: 0=bias, 1=bias+PE, 2=bias+relu, 3=none
// ---------------------------------------------------------------------------
#define GS_SLOT 5120          // floats per slot (A 2560 + B 2560)
#define GSMEM   (4 * GS_SLOT * 4)

template <int EPI>
__global__ __launch_bounds__(256, 2)
void tgemm_kernel(const float* __restrict__ A, const float* __restrict__ W,
                  const float* __restrict__ bias, const float* __restrict__ pe,
                  float* __restrict__ C, int M, int N, int K)
{
    extern __shared__ float smem[];
    const uint32_t sb = smem_u32(smem);

    const int t    = threadIdx.x;
    const int warp = t >> 5;
    const int lane = t & 31;
    const int bm   = blockIdx.y * 128;
    const int bn   = blockIdx.x * 128;
    const int wm   = (warp >> 2) * 64;
    const int wn   = (warp & 3) * 32;
    const int lr   = lane >> 2;
    const int lc   = lane & 3;

    const bool a16 = (K & 3) == 0;   // rows 16B-aligned -> 16B chunks, else 8B (K even)
    const int  NC  = a16 ? 2 : 4;    // chunks per thread per matrix

    // Per-thread load metadata
    int koA[4];                      // float offset within row
    const float* pA[4];
    const float* pB[4];
    bool vB[4];
    uint32_t dA[4], dB[4];           // smem byte offsets within slot
#pragma unroll
    for (int i = 0; i < 4; i++) {
        int c = t + i * 256;
        int r, ko;
        if (a16) { r = (c >> 2) & 127; ko = (c & 3) * 4; }   // c<512 used
        else     { r = c >> 3;         ko = (c & 7) * 2; }   // c<1024 used
        koA[i] = ko;
        pA[i] = A + (size_t)(bm + r) * K + ko;
        int gn = bn + r;
        vB[i] = gn < N;
        pB[i] = W + (size_t)(vB[i] ? gn : 0) * K + ko;
        dA[i] = (uint32_t)((r * 20 + ko) * 4);
        dB[i] = (uint32_t)((2560 + r * 20 + ko) * 4);
    }

    const int nt = (K + 15) / 16;

    auto issue = [&](int kt) {
        const int k0 = kt * 16;
        const uint32_t so = sb + (uint32_t)((kt & 3) * GS_SLOT * 4);
        if (a16) {
#pragma unroll
            for (int i = 0; i < 2; i++) {
                int rem = K - (k0 + koA[i]);
                int sz  = rem >= 4 ? 16 : 0;           // K%4==0 -> full or empty
                const float* sa = sz ? pA[i] + k0 : pA[i];
                cp16(so + dA[i], sa, sz);
                int szb = vB[i] ? sz : 0;
                const float* sbp = szb ? pB[i] + k0 : pB[i];
                cp16(so + dB[i], sbp, szb);
            }
        } else {
#pragma unroll
            for (int i = 0; i < 4; i++) {
                int rem = K - (k0 + koA[i]);
                int sz  = rem >= 2 ? 8 : 0;            // K even -> full or empty
                const float* sa = sz ? pA[i] + k0 : pA[i];
                cp8(so + dA[i], sa, sz);
                int szb = vB[i] ? sz : 0;
                const float* sbp = szb ? pB[i] + k0 : pB[i];
                cp8(so + dB[i], sbp, szb);
            }
        }
    };

    float acc[4][4][4];
#pragma unroll
    for (int i = 0; i < 4; i++)
#pragma unroll
        for (int j = 0; j < 4; j++)
#pragma unroll
            for (int r = 0; r < 4; r++) acc[i][j][r] = 0.f;

    // Prologue: 2 slots in flight
    issue(0); CP_COMMIT();
    if (nt > 1) issue(1);
    CP_COMMIT();

    for (int kt = 0; kt < nt; kt++) {
        if (kt + 2 < nt) issue(kt + 2);
        CP_COMMIT();
        CP_WAIT1();
        __syncthreads();

        const uint32_t* As = (const uint32_t*)(smem + (kt & 3) * GS_SLOT);
        const uint32_t* Bs = As + 2560;

#pragma unroll
        for (int ks = 0; ks < 2; ks++) {
            const int kb = ks * 8;
            uint32_t af[4][4];
#pragma unroll
            for (int i = 0; i < 4; i++) {
                int r = wm + i * 16 + lr;
                af[i][0] = As[r * 20 + kb + lc];
                af[i][1] = As[(r + 8) * 20 + kb + lc];
                af[i][2] = As[r * 20 + kb + lc + 4];
                af[i][3] = As[(r + 8) * 20 + kb + lc + 4];
            }
            uint32_t bf[4][2];
#pragma unroll
            for (int j = 0; j < 4; j++) {
                int c = wn + j * 8 + lr;
                bf[j][0] = Bs[c * 20 + kb + lc];
                bf[j][1] = Bs[c * 20 + kb + lc + 4];
            }
#pragma unroll
            for (int i = 0; i < 4; i++)
#pragma unroll
                for (int j = 0; j < 4; j++) {
                    asm volatile(
                        "mma.sync.aligned.m16n8k8.row.col.f32.tf32.tf32.f32 "
                        "{%0,%1,%2,%3}, {%4,%5,%6,%7}, {%8,%9}, {%0,%1,%2,%3};\n"
                        : "+f"(acc[i][j][0]), "+f"(acc[i][j][1]),
                          "+f"(acc[i][j][2]), "+f"(acc[i][j][3])
                        : "r"(af[i][0]), "r"(af[i][1]), "r"(af[i][2]), "r"(af[i][3]),
                          "r"(bf[j][0]), "r"(bf[j][1]));
                }
        }
    }

    // Epilogue
#pragma unroll
    for (int i = 0; i < 4; i++) {
        int r0 = bm + wm + i * 16 + lr;
#pragma unroll
        for (int j = 0; j < 4; j++) {
            int c = bn + wn + j * 8 + lc * 2;
            if (c < N) {
                float v00 = acc[i][j][0], v01 = acc[i][j][1];
                float v10 = acc[i][j][2], v11 = acc[i][j][3];
                if (EPI != 3) {
                    float b0 = bias[c], b1 = bias[c + 1];
                    v00 += b0; v01 += b1; v10 += b0; v11 += b1;
                }
                if (EPI == 1) {
                    int s0 = r0 % SS, s1 = (r0 + 8) % SS;
                    v00 += pe[(size_t)s0 * DD + c];
                    v01 += pe[(size_t)s0 * DD + c + 1];
                    v10 += pe[(size_t)s1 * DD + c];
                    v11 += pe[(size_t)s1 * DD + c + 1];
                }
                if (EPI == 2) {
                    v00 = fmaxf(v00, 0.f); v01 = fmaxf(v01, 0.f);
                    v10 = fmaxf(v10, 0.f); v11 = fmaxf(v11, 0.f);
                }
                *(float2*)&C[(size_t)r0 * N + c] = make_float2(v00, v01);
                *(float2*)&C[(size_t)(r0 + 8) * N + c] = make_float2(v10, v11);
            }
        }
    }
}

// ---------------------------------------------------------------------------
// Attention: one block per (b, h). 128 threads; threads 0..99 own q rows.
// float4 smem reads (broadcast, conflict-free).
// ---------------------------------------------------------------------------
#define ATT_SMEM ((6400 + 6400 + 100 * 101) * 4)

__global__ __launch_bounds__(128)
void attn_kernel(const float* __restrict__ Q, const float* __restrict__ K,
                 const float* __restrict__ V, float* __restrict__ O)
{
    extern __shared__ float sm[];
    float* Ks = sm;
    float* Vs = sm + 6400;
    float* Sc = sm + 12800;      // stride 101

    const int bh = blockIdx.x;
    const int b  = bh >> 3;
    const int h  = bh & 7;
    const size_t base = ((size_t)b * SS) * DD + (size_t)h * HD;
    const int t = threadIdx.x;

    for (int i = t; i < SS * (HD / 4); i += 128) {
        int s = i >> 4, d4 = i & 15;
        const size_t g = base + (size_t)s * DD + d4 * 4;
        ((float4*)Ks)[i] = *(const float4*)&K[g];
        ((float4*)Vs)[i] = *(const float4*)&V[g];
    }
    __syncthreads();

    if (t < SS) {
        float4 q4[16];
        const float4* qp = (const float4*)&Q[base + (size_t)t * DD];
#pragma unroll
        for (int d = 0; d < 16; d++) q4[d] = qp[d];

        float mx = -1e30f;
        for (int j = 0; j < SS; j++) {
            const float4* kp = (const float4*)&Ks[j * HD];
            float s_ = 0.f;
#pragma unroll
            for (int d = 0; d < 16; d++) {
                float4 kv = kp[d];
                s_ = fmaf(q4[d].x, kv.x, s_);
                s_ = fmaf(q4[d].y, kv.y, s_);
                s_ = fmaf(q4[d].z, kv.z, s_);
                s_ = fmaf(q4[d].w, kv.w, s_);
            }
            s_ *= 0.125f;
            Sc[t * 101 + j] = s_;
            mx = fmaxf(mx, s_);
        }
        float sum = 0.f;
        for (int j = 0; j < SS; j++) {
            float e = __expf(Sc[t * 101 + j] - mx);
            Sc[t * 101 + j] = e;
            sum += e;
        }
        const float inv = 1.f / sum;

        float4 out[16];
#pragma unroll
        for (int d = 0; d < 16; d++) out[d] = make_float4(0.f, 0.f, 0.f, 0.f);
        for (int j = 0; j < SS; j++) {
            float p = Sc[t * 101 + j] * inv;
            const float4* vp = (const float4*)&Vs[j * HD];
#pragma unroll
            for (int d = 0; d < 16; d++) {
                float4 vv = vp[d];
                out[d].x = fmaf(p, vv.x, out[d].x);
                out[d].y = fmaf(p, vv.y, out[d].y);
                out[d].z = fmaf(p, vv.z, out[d].z);
                out[d].w = fmaf(p, vv.w, out[d].w);
            }
        }
        float4* op = (float4*)&O[base + (size_t)t * DD];
#pragma unroll
        for (int d = 0; d < 16; d++) op[d] = out[d];
    }
}

// ---------------------------------------------------------------------------
// AddNorm: Y = X + LayerNorm(X)*w + b
// ---------------------------------------------------------------------------
__global__ __launch_bounds__(128)
void addnorm_kernel(const float* __restrict__ X, const float* __restrict__ w,
                    const float* __restrict__ bn, float* __restrict__ Y)
{
    const int row = blockIdx.x;
    const float* x = X + (size_t)row * DD;
    const int t = threadIdx.x;

    float v[4];
    float s = 0.f, s2 = 0.f;
#pragma unroll
    for (int i = 0; i < 4; i++) {
        v[i] = x[t + 128 * i];
        s  += v[i];
        s2 += v[i] * v[i];
    }
#pragma unroll
    for (int o = 16; o > 0; o >>= 1) {
        s  += __shfl_down_sync(0xffffffffu, s,  o);
        s2 += __shfl_down_sync(0xffffffffu, s2, o);
    }
    __shared__ float red[66];
    const int wid = t >> 5, lid = t & 31;
    if (lid == 0) { red[wid] = s; red[32 + wid] = s2; }
    __syncthreads();
    if (t == 0) {
        float a = 0.f, c = 0.f;
        for (int i = 0; i < 4; i++) { a += red[i]; c += red[32 + i]; }
        red[64] = a; red[65] = c;
    }
    __syncthreads();
    const float mu  = red[64] * (1.f / DD);
    const float var = red[65] * (1.f / DD) - mu * mu;
    const float rs  = rsqrtf(var + 1e-5f);

    float* y = Y + (size_t)row * DD;
#pragma unroll
    for (int i = 0; i < 4; i++) {
        int c = t + 128 * i;
        y[c] = v[i] + (v[i] - mu) * rs * w[c] + bn[c];
    }
}

// ---------------------------------------------------------------------------
// Pooling
// ---------------------------------------------------------------------------
__global__ __launch_bounds__(256)
void pool_kernel(const float* __restrict__ Y2, const float* __restrict__ Hm,
                 const float* __restrict__ Wout, const float* __restrict__ bout,
                 float* __restrict__ out)
{
    const int b = blockIdx.x;
    const int t = threadIdx.x;
    __shared__ float hl[DD];
    __shared__ float lam[SS];
    __shared__ float g[SS];

    const float* Hb = Hm + (size_t)b * SS * DD;
    const float* Yb = Y2 + (size_t)b * SS * DD;

    for (int i = t; i < DD; i += 256) hl[i] = Hb[(size_t)(SS - 1) * DD + i];
    __syncthreads();

    const int wid = t >> 5, lid = t & 31;
    for (int s = wid; s < SS; s += 8) {
        const float* hr = Hb + (size_t)s * DD;
        const float* yr = Yb + (size_t)s * DD;
        float a = 0.f, c = 0.f;
        for (int d = lid; d < DD; d += 32) {
            a += hr[d] * hl[d];
            c += yr[d] * Wout[d];
        }
#pragma unroll
        for (int o = 16; o > 0; o >>= 1) {
            a += __shfl_down_sync(0xffffffffu, a, o);
            c += __shfl_down_sync(0xffffffffu, c, o);
        }
        if (lid == 0) { lam[s] = a; g[s] = c; }
    }
    __syncthreads();

    if (t < 32) {
        float mx = -1e30f;
        for (int s = t; s < SS; s += 32) mx = fmaxf(mx, lam[s]);
#pragma unroll
        for (int o = 16; o > 0; o >>= 1) mx = fmaxf(mx, __shfl_xor_sync(0xffffffffu, mx, o));
        float se = 0.f, sg = 0.f;
        for (int s = t; s < SS; s += 32) {
            float e = __expf(lam[s] - mx);
            se += e;
            sg += e * g[s];
        }
#pragma unroll
        for (int o = 16; o > 0; o >>= 1) {
            se += __shfl_xor_sync(0xffffffffu, se, o);
            sg += __shfl_xor_sync(0xffffffffu, sg, o);
        }
        if (t == 0) out[b] = sg / se + bout[0];
    }
}

// ---------------------------------------------------------------------------
// Launch
// ---------------------------------------------------------------------------
extern "C" void kernel_launch(void* const* d_in, const int* in_sizes, int n_in,
                              void* d_out, int out_size)
{
    const float* src  = (const float*)d_in[0];
    const float* Wf   = (const float*)d_in[1];
    const float* bf   = (const float*)d_in[2];
    const float* pe   = (const float*)d_in[3];
    const float* Wq   = (const float*)d_in[4];
    const float* bq   = (const float*)d_in[5];
    const float* Wk   = (const float*)d_in[6];
    const float* bk   = (const float*)d_in[7];
    const float* Wv   = (const float*)d_in[8];
    const float* bv   = (const float*)d_in[9];
    const float* Wo   = (const float*)d_in[10];
    const float* bo   = (const float*)d_in[11];
    const float* lnw  = (const float*)d_in[12];
    const float* lnb  = (const float*)d_in[13];
    const float* W1   = (const float*)d_in[14];
    const float* b1   = (const float*)d_in[15];
    const float* W2   = (const float*)d_in[16];
    const float* b2   = (const float*)d_in[17];
    const float* Wt   = (const float*)d_in[18];
    const float* Wout = (const float*)d_in[19];
    const float* bout = (const float*)d_in[20];
    float* out = (float*)d_out;

    float *X, *Q, *Kb, *V, *Hh;
    cudaGetSymbolAddress((void**)&X,  g_X);
    cudaGetSymbolAddress((void**)&Q,  g_Q);
    cudaGetSymbolAddress((void**)&Kb, g_K);
    cudaGetSymbolAddress((void**)&V,  g_V);
    cudaGetSymbolAddress((void**)&Hh, g_Hh);

    cudaFuncSetAttribute(attn_kernel, cudaFuncAttributeMaxDynamicSharedMemorySize, ATT_SMEM);
    cudaFuncSetAttribute(tgemm_kernel<0>, cudaFuncAttributeMaxDynamicSharedMemorySize, GSMEM);
    cudaFuncSetAttribute(tgemm_kernel<1>, cudaFuncAttributeMaxDynamicSharedMemorySize, GSMEM);
    cudaFuncSetAttribute(tgemm_kernel<2>, cudaFuncAttributeMaxDynamicSharedMemorySize, GSMEM);
    cudaFuncSetAttribute(tgemm_kernel<3>, cudaFuncAttributeMaxDynamicSharedMemorySize, GSMEM);

    const dim3 gBig(4, MM / 128);   // N=512
    const dim3 gFfn(2, MM / 128);   // N=158
    const dim3 b256(256);

    // 1) X = src @ Wf^T + bf + PE        (K=158 -> 8B cp.async path)
    tgemm_kernel<1><<<gBig, b256, GSMEM>>>(src, Wf, bf, pe, X, MM, DD, FIN);
    // 2) Q,K,V                           (K=512 -> 16B path)
    tgemm_kernel<0><<<gBig, b256, GSMEM>>>(X, Wq, bq, nullptr, Q,  MM, DD, DD);
    tgemm_kernel<0><<<gBig, b256, GSMEM>>>(X, Wk, bk, nullptr, Kb, MM, DD, DD);
    tgemm_kernel<0><<<gBig, b256, GSMEM>>>(X, Wv, bv, nullptr, V,  MM, DD, DD);
    // 3) attention -> X (X dead)
    attn_kernel<<<BB * HH, 128, ATT_SMEM>>>(Q, Kb, V, X);
    // 4) attn_out = attn @ Wo^T + bo -> Q
    tgemm_kernel<0><<<gBig, b256, GSMEM>>>(X, Wo, bo, nullptr, Q, MM, DD, DD);
    // 5) y1 = attn_out + LN(attn_out) -> Kb
    addnorm_kernel<<<MM, 128>>>(Q, lnw, lnb, Kb);
    // 6) hidden = relu(y1 @ W1^T + b1) -> Hh   (N=158)
    tgemm_kernel<2><<<gFfn, b256, GSMEM>>>(Kb, W1, b1, nullptr, Hh, MM, FIN, DD);
    // 7) ffn = hidden @ W2^T + b2 -> V         (K=158 -> 8B path)
    tgemm_kernel<0><<<gBig, b256, GSMEM>>>(Hh, W2, b2, nullptr, V, MM, DD, FIN);
    // 8) y2 = ffn + LN(ffn) -> X
    addnorm_kernel<<<MM, 128>>>(V, lnw, lnb, X);
    // 9) H = y2 @ Wt^T -> Q
    tgemm_kernel<3><<<gBig, b256, GSMEM>>>(X, Wt, nullptr, nullptr, Q, MM, DD, DD);
    // 10) pooling + final projection
    pool_kernel<<<BB, 256>>>(X, Q, Wout, bout, out);
}

// round 13
// speedup vs baseline: 3.5823x; 1.0074x over previous
#include <cuda_runtime.h>
#include <cuda_bf16.h>
#include <cstdint>
#include <cstddef>

// Problem constants
#define BB   2048
#define SS   100
#define FIN  158
#define FPAD 160
#define DD   512
#define HH   8
#define HD   64
#define MM   (BB*SS)           // 204800 rows

// ---------------------------------------------------------------------------
// Scratch (device globals; no allocation allowed)
// ---------------------------------------------------------------------------
__device__ float g_X[(size_t)MM * DD];    // X / attn / y2
__device__ float g_Q[(size_t)MM * DD];    // Q / attn_out / H(temporal)
__device__ float g_K[(size_t)MM * DD];    // K / y1
__device__ float g_V[(size_t)MM * DD];    // V / ffn_out
__device__ float g_Hh[(size_t)MM * FPAD]; // FFN hidden (relu), padded stride 160
__device__ float g_Sp[(size_t)MM * FPAD]; // src padded to K=160
__device__ float g_Wfp[DD * FPAD];        // Wf padded
__device__ float g_W2p[DD * FPAD];        // W2 padded

// ---------------------------------------------------------------------------
// Helpers
// ---------------------------------------------------------------------------
__device__ __forceinline__ uint32_t smem_u32(const void* p) {
    uint32_t a;
    asm("{ .reg .u64 t; cvta.to.shared.u64 t, %1; cvt.u32.u64 %0, t; }" : "=r"(a) : "l"(p));
    return a;
}
__device__ __forceinline__ void cp16(uint32_t dst, const void* src, int sz) {
    asm volatile("cp.async.cg.shared.global [%0], [%1], 16, %2;"
                 :: "r"(dst), "l"(src), "r"(sz));
}
#define CP_COMMIT() asm volatile("cp.async.commit_group;" ::: "memory")
#define CP_WAIT1()  asm volatile("cp.async.wait_group 1;" ::: "memory")

// ---------------------------------------------------------------------------
// Row padding: out[r][0..oc) = in[r][0..ic) then zeros
// ---------------------------------------------------------------------------
__global__ void pad_kernel(const float* __restrict__ in, float* __restrict__ outp,
                           int rows, int ic, int oc)
{
    size_t idx = (size_t)blockIdx.x * blockDim.x + threadIdx.x;
    size_t total = (size_t)rows * oc;
    if (idx < total) {
        int r = (int)(idx / oc), c = (int)(idx % oc);
        outp[idx] = (c < ic) ? in[(size_t)r * ic + c] : 0.f;
    }
}

// ---------------------------------------------------------------------------
// TF32 mma.sync GEMM with cp.async 3-stage pipeline, BK=32.
// C[M,N] = A[M,K] @ W[N,K]^T (+ epilogue).  K % 4 == 0 guaranteed (padded).
// BM=BN=128, 256 threads (8 warps: 2x4), warp tile 64x32.
// smem slot: A[128][36] + B[128][36] floats = 36864 B; 3 slots = 108 KB.
// Loop order (3-slot-safe): wait(kt) -> sync -> issue(kt+2) -> compute(kt).
// EPI: 0=bias, 1=bias+PE, 2=bias+relu, 3=none
// ldc = C row stride; npad: cols in [N,npad) written as 0.
// ---------------------------------------------------------------------------
#define GS_ROW  36
#define GS_HALF (128 * GS_ROW)          // 4608 floats
#define GS_SLOT (2 * GS_HALF)           // 9216 floats
#define GSMEM   (3 * GS_SLOT * 4)       // 110592 bytes

template <int EPI>
__global__ __launch_bounds__(256, 2)
void tgemm_kernel(const float* __restrict__ A, const float* __restrict__ W,
                  const float* __restrict__ bias, const float* __restrict__ pe,
                  float* __restrict__ C, int M, int N, int K, int ldc, int npad)
{
    extern __shared__ float smem[];
    const uint32_t sb = smem_u32(smem);

    const int t    = threadIdx.x;
    const int warp = t >> 5;
    const int lane = t & 31;
    const int bm   = blockIdx.y * 128;
    const int bn   = blockIdx.x * 128;
    const int wm   = (warp >> 2) * 64;
    const int wn   = (warp & 3) * 32;
    const int lr   = lane >> 2;
    const int lc   = lane & 3;

    // Load metadata: 1024 16B-chunks per matrix per slot (128 rows x 8), 4/thread.
    int koA[4];
    const float* pA[4];
    const float* pB[4];
    bool vB[4];
    uint32_t dA[4], dB[4];
#pragma unroll
    for (int i = 0; i < 4; i++) {
        int c = t + i * 256;
        int r = c >> 3, ko = (c & 7) * 4;
        koA[i] = ko;
        pA[i] = A + (size_t)(bm + r) * K + ko;
        int gn = bn + r;
        vB[i] = gn < N;
        pB[i] = W + (size_t)(vB[i] ? gn : 0) * K + ko;
        dA[i] = (uint32_t)((r * GS_ROW + ko) * 4);
        dB[i] = (uint32_t)((GS_HALF + r * GS_ROW + ko) * 4);
    }

    const int nt = (K + 31) / 32;

    auto issue = [&](int kt) {
        const int k0 = kt * 32;
        const uint32_t so = sb + (uint32_t)((kt % 3) * GS_SLOT * 4);
#pragma unroll
        for (int i = 0; i < 4; i++) {
            int sz = (k0 + koA[i] + 4 <= K) ? 16 : 0;
            const float* sa = sz ? pA[i] + k0 : pA[i];
            cp16(so + dA[i], sa, sz);
            int szb = vB[i] ? sz : 0;
            const float* sbp = szb ? pB[i] + k0 : pB[i];
            cp16(so + dB[i], sbp, szb);
        }
    };

    float acc[4][4][4];
#pragma unroll
    for (int i = 0; i < 4; i++)
#pragma unroll
        for (int j = 0; j < 4; j++)
#pragma unroll
            for (int r = 0; r < 4; r++) acc[i][j][r] = 0.f;

    // Prologue: slots 0,1 in flight
    issue(0); CP_COMMIT();
    if (nt > 1) issue(1);
    CP_COMMIT();

    for (int kt = 0; kt < nt; kt++) {
        CP_WAIT1();                 // slot kt arrived (<=1 group pending)
        __syncthreads();            // also: everyone done computing kt-1
        if (kt + 2 < nt) issue(kt + 2);   // overwrites slot (kt-1)%3 -- safe now
        CP_COMMIT();

        const uint32_t* As = (const uint32_t*)(smem + (kt % 3) * GS_SLOT);
        const uint32_t* Bs = As + GS_HALF;

#pragma unroll
        for (int ks = 0; ks < 4; ks++) {
            const int kb = ks * 8;
            uint32_t af[4][4];
#pragma unroll
            for (int i = 0; i < 4; i++) {
                int r = wm + i * 16 + lr;
                af[i][0] = As[r * GS_ROW + kb + lc];
                af[i][1] = As[(r + 8) * GS_ROW + kb + lc];
                af[i][2] = As[r * GS_ROW + kb + lc + 4];
                af[i][3] = As[(r + 8) * GS_ROW + kb + lc + 4];
            }
            uint32_t bf[4][2];
#pragma unroll
            for (int j = 0; j < 4; j++) {
                int c = wn + j * 8 + lr;
                bf[j][0] = Bs[c * GS_ROW + kb + lc];
                bf[j][1] = Bs[c * GS_ROW + kb + lc + 4];
            }
#pragma unroll
            for (int i = 0; i < 4; i++)
#pragma unroll
                for (int j = 0; j < 4; j++) {
                    asm volatile(
                        "mma.sync.aligned.m16n8k8.row.col.f32.tf32.tf32.f32 "
                        "{%0,%1,%2,%3}, {%4,%5,%6,%7}, {%8,%9}, {%0,%1,%2,%3};\n"
                        : "+f"(acc[i][j][0]), "+f"(acc[i][j][1]),
                          "+f"(acc[i][j][2]), "+f"(acc[i][j][3])
                        : "r"(af[i][0]), "r"(af[i][1]), "r"(af[i][2]), "r"(af[i][3]),
                          "r"(bf[j][0]), "r"(bf[j][1]));
                }
        }
    }

    // Epilogue
#pragma unroll
    for (int i = 0; i < 4; i++) {
        int r0 = bm + wm + i * 16 + lr;
#pragma unroll
        for (int j = 0; j < 4; j++) {
            int c = bn + wn + j * 8 + lc * 2;
            if (c < N) {
                float v00 = acc[i][j][0], v01 = acc[i][j][1];
                float v10 = acc[i][j][2], v11 = acc[i][j][3];
                if (EPI != 3) {
                    float b0 = bias[c], b1 = bias[c + 1];
                    v00 += b0; v01 += b1; v10 += b0; v11 += b1;
                }
                if (EPI == 1) {
                    int s0 = r0 % SS, s1 = (r0 + 8) % SS;
                    v00 += pe[(size_t)s0 * DD + c];
                    v01 += pe[(size_t)s0 * DD + c + 1];
                    v10 += pe[(size_t)s1 * DD + c];
                    v11 += pe[(size_t)s1 * DD + c + 1];
                }
                if (EPI == 2) {
                    v00 = fmaxf(v00, 0.f); v01 = fmaxf(v01, 0.f);
                    v10 = fmaxf(v10, 0.f); v11 = fmaxf(v11, 0.f);
                }
                *(float2*)&C[(size_t)r0 * ldc + c] = make_float2(v00, v01);
                *(float2*)&C[(size_t)(r0 + 8) * ldc + c] = make_float2(v10, v11);
            } else if (c < npad) {   // zero-fill pad columns (N even, pairs whole)
                *(float2*)&C[(size_t)r0 * ldc + c] = make_float2(0.f, 0.f);
                *(float2*)&C[(size_t)(r0 + 8) * ldc + c] = make_float2(0.f, 0.f);
            }
        }
    }
}

// ---------------------------------------------------------------------------
// Attention: one block per (b, h). 128 threads; threads 0..99 own q rows.
// ---------------------------------------------------------------------------
#define ATT_SMEM ((6400 + 6400 + 100 * 101) * 4)

__global__ __launch_bounds__(128)
void attn_kernel(const float* __restrict__ Q, const float* __restrict__ K,
                 const float* __restrict__ V, float* __restrict__ O)
{
    extern __shared__ float sm[];
    float* Ks = sm;
    float* Vs = sm + 6400;
    float* Sc = sm + 12800;      // stride 101

    const int bh = blockIdx.x;
    const int b  = bh >> 3;
    const int h  = bh & 7;
    const size_t base = ((size_t)b * SS) * DD + (size_t)h * HD;
    const int t = threadIdx.x;

    for (int i = t; i < SS * (HD / 4); i += 128) {
        int s = i >> 4, d4 = i & 15;
        const size_t g = base + (size_t)s * DD + d4 * 4;
        ((float4*)Ks)[i] = *(const float4*)&K[g];
        ((float4*)Vs)[i] = *(const float4*)&V[g];
    }
    __syncthreads();

    if (t < SS) {
        float4 q4[16];
        const float4* qp = (const float4*)&Q[base + (size_t)t * DD];
#pragma unroll
        for (int d = 0; d < 16; d++) q4[d] = qp[d];

        float mx = -1e30f;
        for (int j = 0; j < SS; j++) {
            const float4* kp = (const float4*)&Ks[j * HD];
            float s_ = 0.f;
#pragma unroll
            for (int d = 0; d < 16; d++) {
                float4 kv = kp[d];
                s_ = fmaf(q4[d].x, kv.x, s_);
                s_ = fmaf(q4[d].y, kv.y, s_);
                s_ = fmaf(q4[d].z, kv.z, s_);
                s_ = fmaf(q4[d].w, kv.w, s_);
            }
            s_ *= 0.125f;
            Sc[t * 101 + j] = s_;
            mx = fmaxf(mx, s_);
        }
        float sum = 0.f;
        for (int j = 0; j < SS; j++) {
            float e = __expf(Sc[t * 101 + j] - mx);
            Sc[t * 101 + j] = e;
            sum += e;
        }
        const float inv = 1.f / sum;

        float4 out[16];
#pragma unroll
        for (int d = 0; d < 16; d++) out[d] = make_float4(0.f, 0.f, 0.f, 0.f);
        for (int j = 0; j < SS; j++) {
            float p = Sc[t * 101 + j] * inv;
            const float4* vp = (const float4*)&Vs[j * HD];
#pragma unroll
            for (int d = 0; d < 16; d++) {
                float4 vv = vp[d];
                out[d].x = fmaf(p, vv.x, out[d].x);
                out[d].y = fmaf(p, vv.y, out[d].y);
                out[d].z = fmaf(p, vv.z, out[d].z);
                out[d].w = fmaf(p, vv.w, out[d].w);
            }
        }
        float4* op = (float4*)&O[base + (size_t)t * DD];
#pragma unroll
        for (int d = 0; d < 16; d++) op[d] = out[d];
    }
}

// ---------------------------------------------------------------------------
// AddNorm: Y = X + LayerNorm(X)*w + b
// ---------------------------------------------------------------------------
__global__ __launch_bounds__(128)
void addnorm_kernel(const float* __restrict__ X, const float* __restrict__ w,
                    const float* __restrict__ bn, float* __restrict__ Y)
{
    const int row = blockIdx.x;
    const float* x = X + (size_t)row * DD;
    const int t = threadIdx.x;

    float v[4];
    float s = 0.f, s2 = 0.f;
#pragma unroll
    for (int i = 0; i < 4; i++) {
        v[i] = x[t + 128 * i];
        s  += v[i];
        s2 += v[i] * v[i];
    }
#pragma unroll
    for (int o = 16; o > 0; o >>= 1) {
        s  += __shfl_down_sync(0xffffffffu, s,  o);
        s2 += __shfl_down_sync(0xffffffffu, s2, o);
    }
    __shared__ float red[66];
    const int wid = t >> 5, lid = t & 31;
    if (lid == 0) { red[wid] = s; red[32 + wid] = s2; }
    __syncthreads();
    if (t == 0) {
        float a = 0.f, c = 0.f;
        for (int i = 0; i < 4; i++) { a += red[i]; c += red[32 + i]; }
        red[64] = a; red[65] = c;
    }
    __syncthreads();
    const float mu  = red[64] * (1.f / DD);
    const float var = red[65] * (1.f / DD) - mu * mu;
    const float rs  = rsqrtf(var + 1e-5f);

    float* y = Y + (size_t)row * DD;
#pragma unroll
    for (int i = 0; i < 4; i++) {
        int c = t + 128 * i;
        y[c] = v[i] + (v[i] - mu) * rs * w[c] + bn[c];
    }
}

// ---------------------------------------------------------------------------
// Pooling
// ---------------------------------------------------------------------------
__global__ __launch_bounds__(256)
void pool_kernel(const float* __restrict__ Y2, const float* __restrict__ Hm,
                 const float* __restrict__ Wout, const float* __restrict__ bout,
                 float* __restrict__ out)
{
    const int b = blockIdx.x;
    const int t = threadIdx.x;
    __shared__ float hl[DD];
    __shared__ float lam[SS];
    __shared__ float g[SS];

    const float* Hb = Hm + (size_t)b * SS * DD;
    const float* Yb = Y2 + (size_t)b * SS * DD;

    for (int i = t; i < DD; i += 256) hl[i] = Hb[(size_t)(SS - 1) * DD + i];
    __syncthreads();

    const int wid = t >> 5, lid = t & 31;
    for (int s = wid; s < SS; s += 8) {
        const float* hr = Hb + (size_t)s * DD;
        const float* yr = Yb + (size_t)s * DD;
        float a = 0.f, c = 0.f;
        for (int d = lid; d < DD; d += 32) {
            a += hr[d] * hl[d];
            c += yr[d] * Wout[d];
        }
#pragma unroll
        for (int o = 16; o > 0; o >>= 1) {
            a += __shfl_down_sync(0xffffffffu, a, o);
            c += __shfl_down_sync(0xffffffffu, c, o);
        }
        if (lid == 0) { lam[s] = a; g[s] = c; }
    }
    __syncthreads();

    if (t < 32) {
        float mx = -1e30f;
        for (int s = t; s < SS; s += 32) mx = fmaxf(mx, lam[s]);
#pragma unroll
        for (int o = 16; o > 0; o >>= 1) mx = fmaxf(mx, __shfl_xor_sync(0xffffffffu, mx, o));
        float se = 0.f, sg = 0.f;
        for (int s = t; s < SS; s += 32) {
            float e = __expf(lam[s] - mx);
            se += e;
            sg += e * g[s];
        }
#pragma unroll
        for (int o = 16; o > 0; o >>= 1) {
            se += __shfl_xor_sync(0xffffffffu, se, o);
            sg += __shfl_xor_sync(0xffffffffu, sg, o);
        }
        if (t == 0) out[b] = sg / se + bout[0];
    }
}

// ---------------------------------------------------------------------------
// Launch
// ---------------------------------------------------------------------------
extern "C" void kernel_launch(void* const* d_in, const int* in_sizes, int n_in,
                              void* d_out, int out_size)
{
    const float* src  = (const float*)d_in[0];
    const float* Wf   = (const float*)d_in[1];
    const float* bf   = (const float*)d_in[2];
    const float* pe   = (const float*)d_in[3];
    const float* Wq   = (const float*)d_in[4];
    const float* bq   = (const float*)d_in[5];
    const float* Wk   = (const float*)d_in[6];
    const float* bk   = (const float*)d_in[7];
    const float* Wv   = (const float*)d_in[8];
    const float* bv   = (const float*)d_in[9];
    const float* Wo   = (const float*)d_in[10];
    const float* bo   = (const float*)d_in[11];
    const float* lnw  = (const float*)d_in[12];
    const float* lnb  = (const float*)d_in[13];
    const float* W1   = (const float*)d_in[14];
    const float* b1   = (const float*)d_in[15];
    const float* W2   = (const float*)d_in[16];
    const float* b2   = (const float*)d_in[17];
    const float* Wt   = (const float*)d_in[18];
    const float* Wout = (const float*)d_in[19];
    const float* bout = (const float*)d_in[20];
    float* out = (float*)d_out;

    float *X, *Q, *Kb, *V, *Hh, *Sp, *Wfp, *W2p;
    cudaGetSymbolAddress((void**)&X,   g_X);
    cudaGetSymbolAddress((void**)&Q,   g_Q);
    cudaGetSymbolAddress((void**)&Kb,  g_K);
    cudaGetSymbolAddress((void**)&V,   g_V);
    cudaGetSymbolAddress((void**)&Hh,  g_Hh);
    cudaGetSymbolAddress((void**)&Sp,  g_Sp);
    cudaGetSymbolAddress((void**)&Wfp, g_Wfp);
    cudaGetSymbolAddress((void**)&W2p, g_W2p);

    cudaFuncSetAttribute(attn_kernel, cudaFuncAttributeMaxDynamicSharedMemorySize, ATT_SMEM);
    cudaFuncSetAttribute(tgemm_kernel<0>, cudaFuncAttributeMaxDynamicSharedMemorySize, GSMEM);
    cudaFuncSetAttribute(tgemm_kernel<1>, cudaFuncAttributeMaxDynamicSharedMemorySize, GSMEM);
    cudaFuncSetAttribute(tgemm_kernel<2>, cudaFuncAttributeMaxDynamicSharedMemorySize, GSMEM);
    cudaFuncSetAttribute(tgemm_kernel<3>, cudaFuncAttributeMaxDynamicSharedMemorySize, GSMEM);

    const dim3 gBig(4, MM / 128);   // N=512
    const dim3 gFfn(2, MM / 128);   // N=158 (pad to 160)
    const dim3 b256(256);

    // 0) pad K=158 operands to 160
    {
        size_t n1 = (size_t)MM * FPAD;
        pad_kernel<<<(unsigned)((n1 + 255) / 256), 256>>>(src, Sp, MM, FIN, FPAD);
        pad_kernel<<<(DD * FPAD + 255) / 256, 256>>>(Wf, Wfp, DD, FIN, FPAD);
        pad_kernel<<<(DD * FPAD + 255) / 256, 256>>>(W2, W2p, DD, FIN, FPAD);
    }

    // 1) X = src_p @ Wf_p^T + bf + PE    (K=160)
    tgemm_kernel<1><<<gBig, b256, GSMEM>>>(Sp, Wfp, bf, pe, X, MM, DD, FPAD, DD, DD);
    // 2) Q,K,V                           (K=512)
    tgemm_kernel<0><<<gBig, b256, GSMEM>>>(X, Wq, bq, nullptr, Q,  MM, DD, DD, DD, DD);
    tgemm_kernel<0><<<gBig, b256, GSMEM>>>(X, Wk, bk, nullptr, Kb, MM, DD, DD, DD, DD);
    tgemm_kernel<0><<<gBig, b256, GSMEM>>>(X, Wv, bv, nullptr, V,  MM, DD, DD, DD, DD);
    // 3) attention -> X (X dead)
    attn_kernel<<<BB * HH, 128, ATT_SMEM>>>(Q, Kb, V, X);
    // 4) attn_out = attn @ Wo^T + bo -> Q
    tgemm_kernel<0><<<gBig, b256, GSMEM>>>(X, Wo, bo, nullptr, Q, MM, DD, DD, DD, DD);
    // 5) y1 = attn_out + LN(attn_out) -> Kb
    addnorm_kernel<<<MM, 128>>>(Q, lnw, lnb, Kb);
    // 6) hidden = relu(y1 @ W1^T + b1) -> Hh padded [MM][160]
    tgemm_kernel<2><<<gFfn, b256, GSMEM>>>(Kb, W1, b1, nullptr, Hh, MM, FIN, DD, FPAD, FPAD);
    // 7) ffn = hidden @ W2_p^T + b2 -> V  (K=160)
    tgemm_kernel<0><<<gBig, b256, GSMEM>>>(Hh, W2p, b2, nullptr, V, MM, DD, FPAD, DD, DD);
    // 8) y2 = ffn + LN(ffn) -> X
    addnorm_kernel<<<MM, 128>>>(V, lnw, lnb, X);
    // 9) H = y2 @ Wt^T -> Q
    tgemm_kernel<3><<<gBig, b256, GSMEM>>>(X, Wt, nullptr, nullptr, Q, MM, DD, DD, DD, DD);
    // 10) pooling + final projection
    pool_kernel<<<BB, 256>>>(X, Q, Wout, bout, out);
}

// round 15
// speedup vs baseline: 3.6999x; 1.0328x over previous
#include <cuda_runtime.h>
#include <cuda_bf16.h>
#include <cstdint>
#include <cstddef>

// Problem constants
#define BB   2048
#define SS   100
#define FIN  158
#define FPAD 160
#define DD   512
#define HH   8
#define HD   64
#define MM   (BB*SS)           // 204800 rows

// ---------------------------------------------------------------------------
// Scratch (device globals; no allocation allowed)
// ---------------------------------------------------------------------------
__device__ float g_X[(size_t)MM * DD];    // X / attn / y2
__device__ float g_Q[(size_t)MM * DD];    // Q / attn_out / H(temporal)
__device__ float g_K[(size_t)MM * DD];    // K / y1
__device__ float g_V[(size_t)MM * DD];    // V / ffn_out
__device__ float g_Hh[(size_t)MM * FPAD]; // FFN hidden (relu), padded stride 160
__device__ float g_Sp[(size_t)MM * FPAD]; // src padded to K=160
__device__ float g_Wfp[DD * FPAD];        // Wf padded
__device__ float g_W2p[DD * FPAD];        // W2 padded

// ---------------------------------------------------------------------------
// Helpers
// ---------------------------------------------------------------------------
__device__ __forceinline__ uint32_t smem_u32(const void* p) {
    uint32_t a;
    asm("{ .reg .u64 t; cvta.to.shared.u64 t, %1; cvt.u32.u64 %0, t; }" : "=r"(a) : "l"(p));
    return a;
}
__device__ __forceinline__ void cp16(uint32_t dst, const void* src, int sz) {
    asm volatile("cp.async.cg.shared.global [%0], [%1], 16, %2;"
                 :: "r"(dst), "l"(src), "r"(sz));
}
#define CP_COMMIT() asm volatile("cp.async.commit_group;" ::: "memory")
#define CP_WAIT1()  asm volatile("cp.async.wait_group 1;" ::: "memory")

// ---------------------------------------------------------------------------
// Row padding: out[r][0..oc) = in[r][0..ic) then zeros
// ---------------------------------------------------------------------------
__global__ void pad_kernel(const float* __restrict__ in, float* __restrict__ outp,
                           int rows, int ic, int oc)
{
    size_t idx = (size_t)blockIdx.x * blockDim.x + threadIdx.x;
    size_t total = (size_t)rows * oc;
    if (idx < total) {
        int r = (int)(idx / oc), c = (int)(idx % oc);
        outp[idx] = (c < ic) ? in[(size_t)r * ic + c] : 0.f;
    }
}

// ---------------------------------------------------------------------------
// TF32 mma.sync GEMM, cp.async 2-slot pipeline, BK=32, 64-bit fragment LDS.
// C[M,N] = A[M,K] @ W[N,K]^T (+ epilogue).  K % 4 == 0 guaranteed (padded).
// BM=BN=128, 256 threads (8 warps: 2x4), warp tile 64x32.
// k-slot reorder: quad thread lc supplies k = {kb+2lc, kb+2lc+1} for BOTH A and B
// (any k<->slot bijection is valid for mma.sync if operands agree) -> float2 LDS.
// Row stride 40 floats: bank base = 8*lr + 8*ks + 2*lc (mod 32) -> conflict-free.
// smem slot: (128 A rows + 128 B rows) * 40 floats = 40960 B; 2 slots = 80 KB.
// EPI: 0=bias, 1=bias+PE, 2=bias+relu, 3=none; ldc = row stride; [N,npad) zeroed.
// ---------------------------------------------------------------------------
#define GS_ROW  40
#define GS_HALF (128 * GS_ROW)          // 5120 floats
#define GS_SLOT (2 * GS_HALF)           // 10240 floats
#define GSMEM   (2 * GS_SLOT * 4)       // 81920 bytes

template <int EPI>
__global__ __launch_bounds__(256, 2)
void tgemm_kernel(const float* __restrict__ A, const float* __restrict__ W,
                  const float* __restrict__ bias, const float* __restrict__ pe,
                  float* __restrict__ C, int M, int N, int K, int ldc, int npad)
{
    extern __shared__ float smem[];
    const uint32_t sb = smem_u32(smem);

    const int t    = threadIdx.x;
    const int warp = t >> 5;
    const int lane = t & 31;
    const int bm   = blockIdx.y * 128;
    const int bn   = blockIdx.x * 128;
    const int wm   = (warp >> 2) * 64;
    const int wn   = (warp & 3) * 32;
    const int lr   = lane >> 2;
    const int lc   = lane & 3;

    // Load metadata: 1024 16B-chunks per matrix per slot (128 rows x 8), 4/thread.
    int koA[4];
    const float* pA[4];
    const float* pB[4];
    bool vB[4];
    uint32_t dA[4], dB[4];
#pragma unroll
    for (int i = 0; i < 4; i++) {
        int c = t + i * 256;
        int r = c >> 3, ko = (c & 7) * 4;
        koA[i] = ko;
        pA[i] = A + (size_t)(bm + r) * K + ko;
        int gn = bn + r;
        vB[i] = gn < N;
        pB[i] = W + (size_t)(vB[i] ? gn : 0) * K + ko;
        dA[i] = (uint32_t)((r * GS_ROW + ko) * 4);
        dB[i] = (uint32_t)((GS_HALF + r * GS_ROW + ko) * 4);
    }

    const int nt = (K + 31) / 32;

    auto issue = [&](int kt) {
        const int k0 = kt * 32;
        const uint32_t so = sb + (uint32_t)((kt & 1) * GS_SLOT * 4);
#pragma unroll
        for (int i = 0; i < 4; i++) {
            int sz = (k0 + koA[i] + 4 <= K) ? 16 : 0;
            const float* sa = sz ? pA[i] + k0 : pA[i];
            cp16(so + dA[i], sa, sz);
            int szb = vB[i] ? sz : 0;
            const float* sbp = szb ? pB[i] + k0 : pB[i];
            cp16(so + dB[i], sbp, szb);
        }
    };

    float acc[4][4][4];
#pragma unroll
    for (int i = 0; i < 4; i++)
#pragma unroll
        for (int j = 0; j < 4; j++)
#pragma unroll
            for (int r = 0; r < 4; r++) acc[i][j][r] = 0.f;

    // Prologue: slots 0,1 in flight (one commit each; empty groups still count)
    issue(0); CP_COMMIT();
    if (nt > 1) issue(1);
    CP_COMMIT();

    for (int kt = 0; kt < nt; kt++) {
        CP_WAIT1();                 // newest group = chunk kt+1 -> chunk kt landed
        __syncthreads();

        const float* As = smem + (kt & 1) * GS_SLOT;
        const float* Bs = As + GS_HALF;
        const int k2 = 2 * lc;

#pragma unroll
        for (int ks = 0; ks < 4; ks++) {
            const int kb = ks * 8 + k2;
            uint2 alo[4], ahi[4];
#pragma unroll
            for (int i = 0; i < 4; i++) {
                int r = wm + i * 16 + lr;
                alo[i] = *(const uint2*)&As[r * GS_ROW + kb];
                ahi[i] = *(const uint2*)&As[(r + 8) * GS_ROW + kb];
            }
            uint2 bv[4];
#pragma unroll
            for (int j = 0; j < 4; j++) {
                int c = wn + j * 8 + lr;
                bv[j] = *(const uint2*)&Bs[c * GS_ROW + kb];
            }
#pragma unroll
            for (int i = 0; i < 4; i++)
#pragma unroll
                for (int j = 0; j < 4; j++) {
                    asm volatile(
                        "mma.sync.aligned.m16n8k8.row.col.f32.tf32.tf32.f32 "
                        "{%0,%1,%2,%3}, {%4,%5,%6,%7}, {%8,%9}, {%0,%1,%2,%3};\n"
                        : "+f"(acc[i][j][0]), "+f"(acc[i][j][1]),
                          "+f"(acc[i][j][2]), "+f"(acc[i][j][3])
                        : "r"(alo[i].x), "r"(ahi[i].x), "r"(alo[i].y), "r"(ahi[i].y),
                          "r"(bv[j].x), "r"(bv[j].y));
                }
        }

        __syncthreads();            // all warps done reading slot kt&1
        if (kt + 2 < nt) issue(kt + 2);
        CP_COMMIT();                // exactly one group per iteration
    }

    // Epilogue
#pragma unroll
    for (int i = 0; i < 4; i++) {
        int r0 = bm + wm + i * 16 + lr;
#pragma unroll
        for (int j = 0; j < 4; j++) {
            int c = bn + wn + j * 8 + lc * 2;
            if (c < N) {
                float v00 = acc[i][j][0], v01 = acc[i][j][1];
                float v10 = acc[i][j][2], v11 = acc[i][j][3];
                if (EPI != 3) {
                    float b0 = bias[c], b1 = bias[c + 1];
                    v00 += b0; v01 += b1; v10 += b0; v11 += b1;
                }
                if (EPI == 1) {
                    int s0 = r0 % SS, s1 = (r0 + 8) % SS;
                    v00 += pe[(size_t)s0 * DD + c];
                    v01 += pe[(size_t)s0 * DD + c + 1];
                    v10 += pe[(size_t)s1 * DD + c];
                    v11 += pe[(size_t)s1 * DD + c + 1];
                }
                if (EPI == 2) {
                    v00 = fmaxf(v00, 0.f); v01 = fmaxf(v01, 0.f);
                    v10 = fmaxf(v10, 0.f); v11 = fmaxf(v11, 0.f);
                }
                *(float2*)&C[(size_t)r0 * ldc + c] = make_float2(v00, v01);
                *(float2*)&C[(size_t)(r0 + 8) * ldc + c] = make_float2(v10, v11);
            } else if (c < npad) {   // zero-fill pad columns
                *(float2*)&C[(size_t)r0 * ldc + c] = make_float2(0.f, 0.f);
                *(float2*)&C[(size_t)(r0 + 8) * ldc + c] = make_float2(0.f, 0.f);
            }
        }
    }
}

// ---------------------------------------------------------------------------
// Attention: one block per (b, h). 128 threads; threads 0..99 own q rows.
// ---------------------------------------------------------------------------
#define ATT_SMEM ((6400 + 6400 + 100 * 101) * 4)

__global__ __launch_bounds__(128)
void attn_kernel(const float* __restrict__ Q, const float* __restrict__ K,
                 const float* __restrict__ V, float* __restrict__ O)
{
    extern __shared__ float sm[];
    float* Ks = sm;
    float* Vs = sm + 6400;
    float* Sc = sm + 12800;      // stride 101

    const int bh = blockIdx.x;
    const int b  = bh >> 3;
    const int h  = bh & 7;
    const size_t base = ((size_t)b * SS) * DD + (size_t)h * HD;
    const int t = threadIdx.x;

    for (int i = t; i < SS * (HD / 4); i += 128) {
        int s = i >> 4, d4 = i & 15;
        const size_t g = base + (size_t)s * DD + d4 * 4;
        ((float4*)Ks)[i] = *(const float4*)&K[g];
        ((float4*)Vs)[i] = *(const float4*)&V[g];
    }
    __syncthreads();

    if (t < SS) {
        float4 q4[16];
        const float4* qp = (const float4*)&Q[base + (size_t)t * DD];
#pragma unroll
        for (int d = 0; d < 16; d++) q4[d] = qp[d];

        float mx = -1e30f;
        for (int j = 0; j < SS; j++) {
            const float4* kp = (const float4*)&Ks[j * HD];
            float s_ = 0.f;
#pragma unroll
            for (int d = 0; d < 16; d++) {
                float4 kv = kp[d];
                s_ = fmaf(q4[d].x, kv.x, s_);
                s_ = fmaf(q4[d].y, kv.y, s_);
                s_ = fmaf(q4[d].z, kv.z, s_);
                s_ = fmaf(q4[d].w, kv.w, s_);
            }
            s_ *= 0.125f;
            Sc[t * 101 + j] = s_;
            mx = fmaxf(mx, s_);
        }
        float sum = 0.f;
        for (int j = 0; j < SS; j++) {
            float e = __expf(Sc[t * 101 + j] - mx);
            Sc[t * 101 + j] = e;
            sum += e;
        }
        const float inv = 1.f / sum;

        float4 out[16];
#pragma unroll
        for (int d = 0; d < 16; d++) out[d] = make_float4(0.f, 0.f, 0.f, 0.f);
        for (int j = 0; j < SS; j++) {
            float p = Sc[t * 101 + j] * inv;
            const float4* vp = (const float4*)&Vs[j * HD];
#pragma unroll
            for (int d = 0; d < 16; d++) {
                float4 vv = vp[d];
                out[d].x = fmaf(p, vv.x, out[d].x);
                out[d].y = fmaf(p, vv.y, out[d].y);
                out[d].z = fmaf(p, vv.z, out[d].z);
                out[d].w = fmaf(p, vv.w, out[d].w);
            }
        }
        float4* op = (float4*)&O[base + (size_t)t * DD];
#pragma unroll
        for (int d = 0; d < 16; d++) op[d] = out[d];
    }
}

// ---------------------------------------------------------------------------
// AddNorm: Y = X + LayerNorm(X)*w + b
// ---------------------------------------------------------------------------
__global__ __launch_bounds__(128)
void addnorm_kernel(const float* __restrict__ X, const float* __restrict__ w,
                    const float* __restrict__ bn, float* __restrict__ Y)
{
    const int row = blockIdx.x;
    const float* x = X + (size_t)row * DD;
    const int t = threadIdx.x;

    float v[4];
    float s = 0.f, s2 = 0.f;
#pragma unroll
    for (int i = 0; i < 4; i++) {
        v[i] = x[t + 128 * i];
        s  += v[i];
        s2 += v[i] * v[i];
    }
#pragma unroll
    for (int o = 16; o > 0; o >>= 1) {
        s  += __shfl_down_sync(0xffffffffu, s,  o);
        s2 += __shfl_down_sync(0xffffffffu, s2, o);
    }
    __shared__ float red[66];
    const int wid = t >> 5, lid = t & 31;
    if (lid == 0) { red[wid] = s; red[32 + wid] = s2; }
    __syncthreads();
    if (t == 0) {
        float a = 0.f, c = 0.f;
        for (int i = 0; i < 4; i++) { a += red[i]; c += red[32 + i]; }
        red[64] = a; red[65] = c;
    }
    __syncthreads();
    const float mu  = red[64] * (1.f / DD);
    const float var = red[65] * (1.f / DD) - mu * mu;
    const float rs  = rsqrtf(var + 1e-5f);

    float* y = Y + (size_t)row * DD;
#pragma unroll
    for (int i = 0; i < 4; i++) {
        int c = t + 128 * i;
        y[c] = v[i] + (v[i] - mu) * rs * w[c] + bn[c];
    }
}

// ---------------------------------------------------------------------------
// Pooling
// ---------------------------------------------------------------------------
__global__ __launch_bounds__(256)
void pool_kernel(const float* __restrict__ Y2, const float* __restrict__ Hm,
                 const float* __restrict__ Wout, const float* __restrict__ bout,
                 float* __restrict__ out)
{
    const int b = blockIdx.x;
    const int t = threadIdx.x;
    __shared__ float hl[DD];
    __shared__ float lam[SS];
    __shared__ float g[SS];

    const float* Hb = Hm + (size_t)b * SS * DD;
    const float* Yb = Y2 + (size_t)b * SS * DD;

    for (int i = t; i < DD; i += 256) hl[i] = Hb[(size_t)(SS - 1) * DD + i];
    __syncthreads();

    const int wid = t >> 5, lid = t & 31;
    for (int s = wid; s < SS; s += 8) {
        const float* hr = Hb + (size_t)s * DD;
        const float* yr = Yb + (size_t)s * DD;
        float a = 0.f, c = 0.f;
        for (int d = lid; d < DD; d += 32) {
            a += hr[d] * hl[d];
            c += yr[d] * Wout[d];
        }
#pragma unroll
        for (int o = 16; o > 0; o >>= 1) {
            a += __shfl_down_sync(0xffffffffu, a, o);
            c += __shfl_down_sync(0xffffffffu, c, o);
        }
        if (lid == 0) { lam[s] = a; g[s] = c; }
    }
    __syncthreads();

    if (t < 32) {
        float mx = -1e30f;
        for (int s = t; s < SS; s += 32) mx = fmaxf(mx, lam[s]);
#pragma unroll
        for (int o = 16; o > 0; o >>= 1) mx = fmaxf(mx, __shfl_xor_sync(0xffffffffu, mx, o));
        float se = 0.f, sg = 0.f;
        for (int s = t; s < SS; s += 32) {
            float e = __expf(lam[s] - mx);
            se += e;
            sg += e * g[s];
        }
#pragma unroll
        for (int o = 16; o > 0; o >>= 1) {
            se += __shfl_xor_sync(0xffffffffu, se, o);
            sg += __shfl_xor_sync(0xffffffffu, sg, o);
        }
        if (t == 0) out[b] = sg / se + bout[0];
    }
}

// ---------------------------------------------------------------------------
// Launch
// ---------------------------------------------------------------------------
extern "C" void kernel_launch(void* const* d_in, const int* in_sizes, int n_in,
                              void* d_out, int out_size)
{
    const float* src  = (const float*)d_in[0];
    const float* Wf   = (const float*)d_in[1];
    const float* bf   = (const float*)d_in[2];
    const float* pe   = (const float*)d_in[3];
    const float* Wq   = (const float*)d_in[4];
    const float* bq   = (const float*)d_in[5];
    const float* Wk   = (const float*)d_in[6];
    const float* bk   = (const float*)d_in[7];
    const float* Wv   = (const float*)d_in[8];
    const float* bv   = (const float*)d_in[9];
    const float* Wo   = (const float*)d_in[10];
    const float* bo   = (const float*)d_in[11];
    const float* lnw  = (const float*)d_in[12];
    const float* lnb  = (const float*)d_in[13];
    const float* W1   = (const float*)d_in[14];
    const float* b1   = (const float*)d_in[15];
    const float* W2   = (const float*)d_in[16];
    const float* b2   = (const float*)d_in[17];
    const float* Wt   = (const float*)d_in[18];
    const float* Wout = (const float*)d_in[19];
    const float* bout = (const float*)d_in[20];
    float* out = (float*)d_out;

    float *X, *Q, *Kb, *V, *Hh, *Sp, *Wfp, *W2p;
    cudaGetSymbolAddress((void**)&X,   g_X);
    cudaGetSymbolAddress((void**)&Q,   g_Q);
    cudaGetSymbolAddress((void**)&Kb,  g_K);
    cudaGetSymbolAddress((void**)&V,   g_V);
    cudaGetSymbolAddress((void**)&Hh,  g_Hh);
    cudaGetSymbolAddress((void**)&Sp,  g_Sp);
    cudaGetSymbolAddress((void**)&Wfp, g_Wfp);
    cudaGetSymbolAddress((void**)&W2p, g_W2p);

    cudaFuncSetAttribute(attn_kernel, cudaFuncAttributeMaxDynamicSharedMemorySize, ATT_SMEM);
    cudaFuncSetAttribute(tgemm_kernel<0>, cudaFuncAttributeMaxDynamicSharedMemorySize, GSMEM);
    cudaFuncSetAttribute(tgemm_kernel<1>, cudaFuncAttributeMaxDynamicSharedMemorySize, GSMEM);
    cudaFuncSetAttribute(tgemm_kernel<2>, cudaFuncAttributeMaxDynamicSharedMemorySize, GSMEM);
    cudaFuncSetAttribute(tgemm_kernel<3>, cudaFuncAttributeMaxDynamicSharedMemorySize, GSMEM);

    const dim3 gBig(4, MM / 128);   // N=512
    const dim3 gFfn(2, MM / 128);   // N=158 (pad to 160)
    const dim3 b256(256);

    // 0) pad K=158 operands to 160
    {
        size_t n1 = (size_t)MM * FPAD;
        pad_kernel<<<(unsigned)((n1 + 255) / 256), 256>>>(src, Sp, MM, FIN, FPAD);
        pad_kernel<<<(DD * FPAD + 255) / 256, 256>>>(Wf, Wfp, DD, FIN, FPAD);
        pad_kernel<<<(DD * FPAD + 255) / 256, 256>>>(W2, W2p, DD, FIN, FPAD);
    }

    // 1) X = src_p @ Wf_p^T + bf + PE    (K=160)
    tgemm_kernel<1><<<gBig, b256, GSMEM>>>(Sp, Wfp, bf, pe, X, MM, DD, FPAD, DD, DD);
    // 2) Q,K,V                           (K=512)
    tgemm_kernel<0><<<gBig, b256, GSMEM>>>(X, Wq, bq, nullptr, Q,  MM, DD, DD, DD, DD);
    tgemm_kernel<0><<<gBig, b256, GSMEM>>>(X, Wk, bk, nullptr, Kb, MM, DD, DD, DD, DD);
    tgemm_kernel<0><<<gBig, b256, GSMEM>>>(X, Wv, bv, nullptr, V,  MM, DD, DD, DD, DD);
    // 3) attention -> X (X dead)
    attn_kernel<<<BB * HH, 128, ATT_SMEM>>>(Q, Kb, V, X);
    // 4) attn_out = attn @ Wo^T + bo -> Q
    tgemm_kernel<0><<<gBig, b256, GSMEM>>>(X, Wo, bo, nullptr, Q, MM, DD, DD, DD, DD);
    // 5) y1 = attn_out + LN(attn_out) -> Kb
    addnorm_kernel<<<MM, 128>>>(Q, lnw, lnb, Kb);
    // 6) hidden = relu(y1 @ W1^T + b1) -> Hh padded [MM][160]
    tgemm_kernel<2><<<gFfn, b256, GSMEM>>>(Kb, W1, b1, nullptr, Hh, MM, FIN, DD, FPAD, FPAD);
    // 7) ffn = hidden @ W2_p^T + b2 -> V  (K=160)
    tgemm_kernel<0><<<gBig, b256, GSMEM>>>(Hh, W2p, b2, nullptr, V, MM, DD, FPAD, DD, DD);
    // 8) y2 = ffn + LN(ffn) -> X
    addnorm_kernel<<<MM, 128>>>(V, lnw, lnb, X);
    // 9) H = y2 @ Wt^T -> Q
    tgemm_kernel<3><<<gBig, b256, GSMEM>>>(X, Wt, nullptr, nullptr, Q, MM, DD, DD, DD, DD);
    // 10) pooling + final projection
    pool_kernel<<<BB, 256>>>(X, Q, Wout, bout, out);
}

// round 17
// speedup vs baseline: 3.8866x; 1.0504x over previous
#include <cuda_runtime.h>
#include <cuda_bf16.h>
#include <cstdint>
#include <cstddef>

// Problem constants
#define BB   2048
#define SS   100
#define FIN  158
#define FPAD 160
#define DD   512
#define HH   8
#define HD   64
#define MM   (BB*SS)           // 204800 rows

// ---------------------------------------------------------------------------
// Scratch (device globals; no allocation allowed)
// ---------------------------------------------------------------------------
__device__ float g_X[(size_t)MM * DD];    // X / attn / y2
__device__ float g_Q[(size_t)MM * DD];    // Q / attn_out / H(temporal)
__device__ float g_K[(size_t)MM * DD];    // K / y1
__device__ float g_V[(size_t)MM * DD];    // V / ffn_out
__device__ float g_Hh[(size_t)MM * FPAD]; // FFN hidden (relu), padded stride 160
__device__ float g_Sp[(size_t)MM * FPAD]; // src padded to K=160
__device__ float g_Wfp[DD * FPAD];        // Wf padded
__device__ float g_W2p[DD * FPAD];        // W2 padded

// ---------------------------------------------------------------------------
// Helpers
// ---------------------------------------------------------------------------
__device__ __forceinline__ uint32_t smem_u32(const void* p) {
    uint32_t a;
    asm("{ .reg .u64 t; cvta.to.shared.u64 t, %1; cvt.u32.u64 %0, t; }" : "=r"(a) : "l"(p));
    return a;
}
__device__ __forceinline__ void cp16(uint32_t dst, const void* src, int sz) {
    asm volatile("cp.async.cg.shared.global [%0], [%1], 16, %2;"
                 :: "r"(dst), "l"(src), "r"(sz));
}
#define CP_COMMIT() asm volatile("cp.async.commit_group;" ::: "memory")
#define CP_WAIT1()  asm volatile("cp.async.wait_group 1;" ::: "memory")

// ---------------------------------------------------------------------------
// Row padding: out[r][0..oc) = in[r][0..ic) then zeros
// ---------------------------------------------------------------------------
__global__ void pad_kernel(const float* __restrict__ in, float* __restrict__ outp,
                           int rows, int ic, int oc)
{
    size_t idx = (size_t)blockIdx.x * blockDim.x + threadIdx.x;
    size_t total = (size_t)rows * oc;
    if (idx < total) {
        int r = (int)(idx / oc), c = (int)(idx % oc);
        outp[idx] = (c < ic) ? in[(size_t)r * ic + c] : 0.f;
    }
}

// ---------------------------------------------------------------------------
// TF32 mma.sync GEMM, cp.async 2-slot pipeline, BK=32, 64-bit fragment LDS.
// C[M,N] = A[M,K] @ W[N,K]^T (+ epilogue).  K % 4 == 0 guaranteed (padded).
// BM=BN=128, 128 threads (4 warps: 2x2), warp tile 64x64.
// Rationale: fragment smem traffic per warp ~ (m+n), MMAs ~ m*n. 64x64 tiles
// cut CTA fragment reads 96KB -> 64KB per K-tile, doubling MMA per LDS byte.
// k-slot reorder: quad thread lc supplies k = {kb+2lc, kb+2lc+1} for BOTH A and B
// (any k<->slot bijection is valid for mma.sync if operands agree) -> float2 LDS.
// Row stride 40 floats: bank base = 8*lr + 2*lc (mod 32) -> conflict-free halves.
// smem slot: (128 A rows + 128 B rows) * 40 floats = 40960 B; 2 slots = 80 KB.
// EPI: 0=bias, 1=bias+PE, 2=bias+relu, 3=none; ldc = row stride; [N,npad) zeroed.
// ---------------------------------------------------------------------------
#define GS_ROW  40
#define GS_HALF (128 * GS_ROW)          // 5120 floats
#define GS_SLOT (2 * GS_HALF)           // 10240 floats
#define GSMEM   (2 * GS_SLOT * 4)       // 81920 bytes

template <int EPI>
__global__ __launch_bounds__(128, 2)
void tgemm_kernel(const float* __restrict__ A, const float* __restrict__ W,
                  const float* __restrict__ bias, const float* __restrict__ pe,
                  float* __restrict__ C, int M, int N, int K, int ldc, int npad)
{
    extern __shared__ float smem[];
    const uint32_t sb = smem_u32(smem);

    const int t    = threadIdx.x;
    const int warp = t >> 5;
    const int lane = t & 31;
    const int bm   = blockIdx.y * 128;
    const int bn   = blockIdx.x * 128;
    const int wm   = (warp >> 1) * 64;   // 0 or 64
    const int wn   = (warp & 1) * 64;    // 0 or 64
    const int lr   = lane >> 2;
    const int lc   = lane & 3;

    // Load metadata: 1024 16B-chunks per matrix per slot (128 rows x 8).
    // 128 threads -> 8 chunks per thread per matrix: row = (t>>3)+16i, col (t&7)*4.
    const int r0t = t >> 3;
    const int ko  = (t & 7) * 4;
    const float* pAb = A + (size_t)(bm + r0t) * K + ko;
    const float* pBb = W + (size_t)(bn + r0t) * K + ko;   // may be clamped per i
    const size_t strideAB = (size_t)16 * K;
    bool vB[8];
#pragma unroll
    for (int i = 0; i < 8; i++) vB[i] = (bn + r0t + 16 * i) < N;
    const uint32_t dA0 = (uint32_t)((r0t * GS_ROW + ko) * 4);
    const uint32_t dB0 = dA0 + GS_HALF * 4;

    const int nt = (K + 31) / 32;

    auto issue = [&](int kt) {
        const int k0 = kt * 32;
        const int sz = (k0 + ko + 4 <= K) ? 16 : 0;   // K%4==0 -> full or empty
        const int koff = sz ? k0 : 0;                 // keep address in-bounds
        const uint32_t so = sb + (uint32_t)((kt & 1) * GS_SLOT * 4);
#pragma unroll
        for (int i = 0; i < 8; i++) {
            cp16(so + dA0 + i * (16 * GS_ROW * 4), pAb + i * strideAB + koff, sz);
            int szb = vB[i] ? sz : 0;
            cp16(so + dB0 + i * (16 * GS_ROW * 4), pBb + i * strideAB + (szb ? k0 : 0), szb);
        }
    };

    float acc[4][8][4];
#pragma unroll
    for (int i = 0; i < 4; i++)
#pragma unroll
        for (int j = 0; j < 8; j++)
#pragma unroll
            for (int r = 0; r < 4; r++) acc[i][j][r] = 0.f;

    // Prologue: slots 0,1 in flight (one commit each; empty groups still count)
    issue(0); CP_COMMIT();
    if (nt > 1) issue(1);
    CP_COMMIT();

    for (int kt = 0; kt < nt; kt++) {
        CP_WAIT1();                 // newest group = chunk kt+1 -> chunk kt landed
        __syncthreads();

        const float* As = smem + (kt & 1) * GS_SLOT;
        const float* Bs = As + GS_HALF;
        const int k2 = 2 * lc;

#pragma unroll
        for (int ks = 0; ks < 4; ks++) {
            const int kb = ks * 8 + k2;
            uint2 alo[4], ahi[4];
#pragma unroll
            for (int i = 0; i < 4; i++) {
                int r = wm + i * 16 + lr;
                alo[i] = *(const uint2*)&As[r * GS_ROW + kb];
                ahi[i] = *(const uint2*)&As[(r + 8) * GS_ROW + kb];
            }
            uint2 bv[8];
#pragma unroll
            for (int j = 0; j < 8; j++) {
                int c = wn + j * 8 + lr;
                bv[j] = *(const uint2*)&Bs[c * GS_ROW + kb];
            }
#pragma unroll
            for (int i = 0; i < 4; i++)
#pragma unroll
                for (int j = 0; j < 8; j++) {
                    asm volatile(
                        "mma.sync.aligned.m16n8k8.row.col.f32.tf32.tf32.f32 "
                        "{%0,%1,%2,%3}, {%4,%5,%6,%7}, {%8,%9}, {%0,%1,%2,%3};\n"
                        : "+f"(acc[i][j][0]), "+f"(acc[i][j][1]),
                          "+f"(acc[i][j][2]), "+f"(acc[i][j][3])
                        : "r"(alo[i].x), "r"(ahi[i].x), "r"(alo[i].y), "r"(ahi[i].y),
                          "r"(bv[j].x), "r"(bv[j].y));
                }
        }

        __syncthreads();            // all warps done reading slot kt&1
        if (kt + 2 < nt) issue(kt + 2);
        CP_COMMIT();                // exactly one group per iteration
    }

    // Epilogue
#pragma unroll
    for (int i = 0; i < 4; i++) {
        int r0 = bm + wm + i * 16 + lr;
#pragma unroll
        for (int j = 0; j < 8; j++) {
            int c = bn + wn + j * 8 + lc * 2;
            if (c < N) {
                float v00 = acc[i][j][0], v01 = acc[i][j][1];
                float v10 = acc[i][j][2], v11 = acc[i][j][3];
                if (EPI != 3) {
                    float b0 = bias[c], b1 = bias[c + 1];
                    v00 += b0; v01 += b1; v10 += b0; v11 += b1;
                }
                if (EPI == 1) {
                    int s0 = r0 % SS, s1 = (r0 + 8) % SS;
                    v00 += pe[(size_t)s0 * DD + c];
                    v01 += pe[(size_t)s0 * DD + c + 1];
                    v10 += pe[(size_t)s1 * DD + c];
                    v11 += pe[(size_t)s1 * DD + c + 1];
                }
                if (EPI == 2) {
                    v00 = fmaxf(v00, 0.f); v01 = fmaxf(v01, 0.f);
                    v10 = fmaxf(v10, 0.f); v11 = fmaxf(v11, 0.f);
                }
                *(float2*)&C[(size_t)r0 * ldc + c] = make_float2(v00, v01);
                *(float2*)&C[(size_t)(r0 + 8) * ldc + c] = make_float2(v10, v11);
            } else if (c < npad) {   // zero-fill pad columns
                *(float2*)&C[(size_t)r0 * ldc + c] = make_float2(0.f, 0.f);
                *(float2*)&C[(size_t)(r0 + 8) * ldc + c] = make_float2(0.f, 0.f);
            }
        }
    }
}

// ---------------------------------------------------------------------------
// Attention: one block per (b, h). 128 threads; threads 0..99 own q rows.
// ---------------------------------------------------------------------------
#define ATT_SMEM ((6400 + 6400 + 100 * 101) * 4)

__global__ __launch_bounds__(128)
void attn_kernel(const float* __restrict__ Q, const float* __restrict__ K,
                 const float* __restrict__ V, float* __restrict__ O)
{
    extern __shared__ float sm[];
    float* Ks = sm;
    float* Vs = sm + 6400;
    float* Sc = sm + 12800;      // stride 101

    const int bh = blockIdx.x;
    const int b  = bh >> 3;
    const int h  = bh & 7;
    const size_t base = ((size_t)b * SS) * DD + (size_t)h * HD;
    const int t = threadIdx.x;

    for (int i = t; i < SS * (HD / 4); i += 128) {
        int s = i >> 4, d4 = i & 15;
        const size_t g = base + (size_t)s * DD + d4 * 4;
        ((float4*)Ks)[i] = *(const float4*)&K[g];
        ((float4*)Vs)[i] = *(const float4*)&V[g];
    }
    __syncthreads();

    if (t < SS) {
        float4 q4[16];
        const float4* qp = (const float4*)&Q[base + (size_t)t * DD];
#pragma unroll
        for (int d = 0; d < 16; d++) q4[d] = qp[d];

        float mx = -1e30f;
        for (int j = 0; j < SS; j++) {
            const float4* kp = (const float4*)&Ks[j * HD];
            float s_ = 0.f;
#pragma unroll
            for (int d = 0; d < 16; d++) {
                float4 kv = kp[d];
                s_ = fmaf(q4[d].x, kv.x, s_);
                s_ = fmaf(q4[d].y, kv.y, s_);
                s_ = fmaf(q4[d].z, kv.z, s_);
                s_ = fmaf(q4[d].w, kv.w, s_);
            }
            s_ *= 0.125f;
            Sc[t * 101 + j] = s_;
            mx = fmaxf(mx, s_);
        }
        float sum = 0.f;
        for (int j = 0; j < SS; j++) {
            float e = __expf(Sc[t * 101 + j] - mx);
            Sc[t * 101 + j] = e;
            sum += e;
        }
        const float inv = 1.f / sum;

        float4 out[16];
#pragma unroll
        for (int d = 0; d < 16; d++) out[d] = make_float4(0.f, 0.f, 0.f, 0.f);
        for (int j = 0; j < SS; j++) {
            float p = Sc[t * 101 + j] * inv;
            const float4* vp = (const float4*)&Vs[j * HD];
#pragma unroll
            for (int d = 0; d < 16; d++) {
                float4 vv = vp[d];
                out[d].x = fmaf(p, vv.x, out[d].x);
                out[d].y = fmaf(p, vv.y, out[d].y);
                out[d].z = fmaf(p, vv.z, out[d].z);
                out[d].w = fmaf(p, vv.w, out[d].w);
            }
        }
        float4* op = (float4*)&O[base + (size_t)t * DD];
#pragma unroll
        for (int d = 0; d < 16; d++) op[d] = out[d];
    }
}

// ---------------------------------------------------------------------------
// AddNorm: Y = X + LayerNorm(X)*w + b
// ---------------------------------------------------------------------------
__global__ __launch_bounds__(128)
void addnorm_kernel(const float* __restrict__ X, const float* __restrict__ w,
                    const float* __restrict__ bn, float* __restrict__ Y)
{
    const int row = blockIdx.x;
    const float* x = X + (size_t)row * DD;
    const int t = threadIdx.x;

    float v[4];
    float s = 0.f, s2 = 0.f;
#pragma unroll
    for (int i = 0; i < 4; i++) {
        v[i] = x[t + 128 * i];
        s  += v[i];
        s2 += v[i] * v[i];
    }
#pragma unroll
    for (int o = 16; o > 0; o >>= 1) {
        s  += __shfl_down_sync(0xffffffffu, s,  o);
        s2 += __shfl_down_sync(0xffffffffu, s2, o);
    }
    __shared__ float red[66];
    const int wid = t >> 5, lid = t & 31;
    if (lid == 0) { red[wid] = s; red[32 + wid] = s2; }
    __syncthreads();
    if (t == 0) {
        float a = 0.f, c = 0.f;
        for (int i = 0; i < 4; i++) { a += red[i]; c += red[32 + i]; }
        red[64] = a; red[65] = c;
    }
    __syncthreads();
    const float mu  = red[64] * (1.f / DD);
    const float var = red[65] * (1.f / DD) - mu * mu;
    const float rs  = rsqrtf(var + 1e-5f);

    float* y = Y + (size_t)row * DD;
#pragma unroll
    for (int i = 0; i < 4; i++) {
        int c = t + 128 * i;
        y[c] = v[i] + (v[i] - mu) * rs * w[c] + bn[c];
    }
}

// ---------------------------------------------------------------------------
// Pooling
// ---------------------------------------------------------------------------
__global__ __launch_bounds__(256)
void pool_kernel(const float* __restrict__ Y2, const float* __restrict__ Hm,
                 const float* __restrict__ Wout, const float* __restrict__ bout,
                 float* __restrict__ out)
{
    const int b = blockIdx.x;
    const int t = threadIdx.x;
    __shared__ float hl[DD];
    __shared__ float lam[SS];
    __shared__ float g[SS];

    const float* Hb = Hm + (size_t)b * SS * DD;
    const float* Yb = Y2 + (size_t)b * SS * DD;

    for (int i = t; i < DD; i += 256) hl[i] = Hb[(size_t)(SS - 1) * DD + i];
    __syncthreads();

    const int wid = t >> 5, lid = t & 31;
    for (int s = wid; s < SS; s += 8) {
        const float* hr = Hb + (size_t)s * DD;
        const float* yr = Yb + (size_t)s * DD;
        float a = 0.f, c = 0.f;
        for (int d = lid; d < DD; d += 32) {
            a += hr[d] * hl[d];
            c += yr[d] * Wout[d];
        }
#pragma unroll
        for (int o = 16; o > 0; o >>= 1) {
            a += __shfl_down_sync(0xffffffffu, a, o);
            c += __shfl_down_sync(0xffffffffu, c, o);
        }
        if (lid == 0) { lam[s] = a; g[s] = c; }
    }
    __syncthreads();

    if (t < 32) {
        float mx = -1e30f;
        for (int s = t; s < SS; s += 32) mx = fmaxf(mx, lam[s]);
#pragma unroll
        for (int o = 16; o > 0; o >>= 1) mx = fmaxf(mx, __shfl_xor_sync(0xffffffffu, mx, o));
        float se = 0.f, sg = 0.f;
        for (int s = t; s < SS; s += 32) {
            float e = __expf(lam[s] - mx);
            se += e;
            sg += e * g[s];
        }
#pragma unroll
        for (int o = 16; o > 0; o >>= 1) {
            se += __shfl_xor_sync(0xffffffffu, se, o);
            sg += __shfl_xor_sync(0xffffffffu, sg, o);
        }
        if (t == 0) out[b] = sg / se + bout[0];
    }
}

// ---------------------------------------------------------------------------
// Launch
// ---------------------------------------------------------------------------
extern "C" void kernel_launch(void* const* d_in, const int* in_sizes, int n_in,
                              void* d_out, int out_size)
{
    const float* src  = (const float*)d_in[0];
    const float* Wf   = (const float*)d_in[1];
    const float* bf   = (const float*)d_in[2];
    const float* pe   = (const float*)d_in[3];
    const float* Wq   = (const float*)d_in[4];
    const float* bq   = (const float*)d_in[5];
    const float* Wk   = (const float*)d_in[6];
    const float* bk   = (const float*)d_in[7];
    const float* Wv   = (const float*)d_in[8];
    const float* bv   = (const float*)d_in[9];
    const float* Wo   = (const float*)d_in[10];
    const float* bo   = (const float*)d_in[11];
    const float* lnw  = (const float*)d_in[12];
    const float* lnb  = (const float*)d_in[13];
    const float* W1   = (const float*)d_in[14];
    const float* b1   = (const float*)d_in[15];
    const float* W2   = (const float*)d_in[16];
    const float* b2   = (const float*)d_in[17];
    const float* Wt   = (const float*)d_in[18];
    const float* Wout = (const float*)d_in[19];
    const float* bout = (const float*)d_in[20];
    float* out = (float*)d_out;

    float *X, *Q, *Kb, *V, *Hh, *Sp, *Wfp, *W2p;
    cudaGetSymbolAddress((void**)&X,   g_X);
    cudaGetSymbolAddress((void**)&Q,   g_Q);
    cudaGetSymbolAddress((void**)&Kb,  g_K);
    cudaGetSymbolAddress((void**)&V,   g_V);
    cudaGetSymbolAddress((void**)&Hh,  g_Hh);
    cudaGetSymbolAddress((void**)&Sp,  g_Sp);
    cudaGetSymbolAddress((void**)&Wfp, g_Wfp);
    cudaGetSymbolAddress((void**)&W2p, g_W2p);

    cudaFuncSetAttribute(attn_kernel, cudaFuncAttributeMaxDynamicSharedMemorySize, ATT_SMEM);
    cudaFuncSetAttribute(tgemm_kernel<0>, cudaFuncAttributeMaxDynamicSharedMemorySize, GSMEM);
    cudaFuncSetAttribute(tgemm_kernel<1>, cudaFuncAttributeMaxDynamicSharedMemorySize, GSMEM);
    cudaFuncSetAttribute(tgemm_kernel<2>, cudaFuncAttributeMaxDynamicSharedMemorySize, GSMEM);
    cudaFuncSetAttribute(tgemm_kernel<3>, cudaFuncAttributeMaxDynamicSharedMemorySize, GSMEM);

    const dim3 gBig(4, MM / 128);   // N=512
    const dim3 gFfn(2, MM / 128);   // N=158 (pad to 160)
    const dim3 b128(128);

    // 0) pad K=158 operands to 160
    {
        size_t n1 = (size_t)MM * FPAD;
        pad_kernel<<<(unsigned)((n1 + 255) / 256), 256>>>(src, Sp, MM, FIN, FPAD);
        pad_kernel<<<(DD * FPAD + 255) / 256, 256>>>(Wf, Wfp, DD, FIN, FPAD);
        pad_kernel<<<(DD * FPAD + 255) / 256, 256>>>(W2, W2p, DD, FIN, FPAD);
    }

    // 1) X = src_p @ Wf_p^T + bf + PE    (K=160)
    tgemm_kernel<1><<<gBig, b128, GSMEM>>>(Sp, Wfp, bf, pe, X, MM, DD, FPAD, DD, DD);
    // 2) Q,K,V                           (K=512)
    tgemm_kernel<0><<<gBig, b128, GSMEM>>>(X, Wq, bq, nullptr, Q,  MM, DD, DD, DD, DD);
    tgemm_kernel<0><<<gBig, b128, GSMEM>>>(X, Wk, bk, nullptr, Kb, MM, DD, DD, DD, DD);
    tgemm_kernel<0><<<gBig, b128, GSMEM>>>(X, Wv, bv, nullptr, V,  MM, DD, DD, DD, DD);
    // 3) attention -> X (X dead)
    attn_kernel<<<BB * HH, 128, ATT_SMEM>>>(Q, Kb, V, X);
    // 4) attn_out = attn @ Wo^T + bo -> Q
    tgemm_kernel<0><<<gBig, b128, GSMEM>>>(X, Wo, bo, nullptr, Q, MM, DD, DD, DD, DD);
    // 5) y1 = attn_out + LN(attn_out) -> Kb
    addnorm_kernel<<<MM, 128>>>(Q, lnw, lnb, Kb);
    // 6) hidden = relu(y1 @ W1^T + b1) -> Hh padded [MM][160]
    tgemm_kernel<2><<<gFfn, b128, GSMEM>>>(Kb, W1, b1, nullptr, Hh, MM, FIN, DD, FPAD, FPAD);
    // 7) ffn = hidden @ W2_p^T + b2 -> V  (K=160)
    tgemm_kernel<0><<<gBig, b128, GSMEM>>>(Hh, W2p, b2, nullptr, V, MM, DD, FPAD, DD, DD);
    // 8) y2 = ffn + LN(ffn) -> X
    addnorm_kernel<<<MM, 128>>>(V, lnw, lnb, X);
    // 9) H = y2 @ Wt^T -> Q
    tgemm_kernel<3><<<gBig, b128, GSMEM>>>(X, Wt, nullptr, nullptr, Q, MM, DD, DD, DD, DD);
    // 10) pooling + final projection
    pool_kernel<<<BB, 256>>>(X, Q, Wout, bout, out);
}